// round 14
// baseline (speedup 1.0000x reference)
#include <cuda_runtime.h>
#include <cuda_fp16.h>
#include <math.h>

#define BNODES 8192
#define HDIM   256
#define NEDGE  131072
#define NLAYER 4
#define SLOTCAP 128

// fp32 scratch
__device__ float g_h [BNODES * HDIM];
__device__ float g_t1[BNODES * HDIM];
__device__ int   g_cnt[BNODES];
__device__ int   g_slot[BNODES * SLOTCAP];
__device__ float g_psum[256 * HDIM];
__device__ float g_psq [256 * HDIM];
__device__ float g_stat[2 * HDIM];
__device__ float g_statid[2 * HDIM];
__device__ float g_bcat[HDIM];
// fp16 scratch
__device__ __half g_w16[3442688];
__device__ __half g_xpe16[BNODES * 136];
__device__ __half g_wcat16[HDIM * 136];
__device__ __half g_h16[BNODES * HDIM];
__device__ __half g_t1h[BNODES * 1024];
__device__ __half g_t2h[BNODES * HDIM];

#define OFF_GCN  0
#define OFF_AIN  262144
#define OFF_AOUT 1048576
#define OFF_FFN1 1310720
#define OFF_FFN2 2359296
#define OFF_HW1  3407872

__device__ __forceinline__ float gelu_f(float x) {
    return 0.5f * x * (1.0f + erff(x * 0.70710678118654752f));
}

__device__ __forceinline__ void cp_async16(void* smem_dst, const void* gmem_src) {
    unsigned s = (unsigned)__cvta_generic_to_shared(smem_dst);
    asm volatile("cp.async.cg.shared.global [%0], [%1], 16;\n" :: "r"(s), "l"(gmem_src));
}
#define CP_COMMIT() asm volatile("cp.async.commit_group;\n" ::: "memory")
#define CP_WAIT1()  asm volatile("cp.async.wait_group 1;\n" ::: "memory")
#define CP_WAIT0()  asm volatile("cp.async.wait_group 0;\n" ::: "memory")

#define MMA_F16(c0,c1,c2,c3, a0,a1,a2,a3, b0,b1)                           \
    asm volatile(                                                          \
        "mma.sync.aligned.m16n8k16.row.col.f32.f16.f16.f32 "               \
        "{%0,%1,%2,%3}, {%4,%5,%6,%7}, {%8,%9}, {%0,%1,%2,%3};\n"          \
        : "+f"(c0), "+f"(c1), "+f"(c2), "+f"(c3)                            \
        : "r"(a0), "r"(a1), "r"(a2), "r"(a3), "r"(b0), "r"(b1))

#define LDSM4(r0,r1,r2,r3, addr)                                            \
    asm volatile("ldmatrix.sync.aligned.m8n8.x4.shared.b16 {%0,%1,%2,%3}, [%4];" \
        : "=r"(r0), "=r"(r1), "=r"(r2), "=r"(r3) : "r"(addr))

#define LDSM4T(r0,r1,r2,r3, addr)                                           \
    asm volatile("ldmatrix.sync.aligned.m8n8.x4.trans.shared.b16 {%0,%1,%2,%3}, [%4];" \
        : "=r"(r0), "=r"(r1), "=r"(r2), "=r"(r3) : "r"(addr))

// ---------------- batched fp32 -> fp16 convert (weights) -------------------
#define NSEG 6
struct ConvSegs {
    const float* src[NSEG];
    __half*      dst[NSEG];
    int          cum4[NSEG + 1];
};

__global__ void f2h_multi_kernel(ConvSegs segs, int total4) {
    int i = blockIdx.x * 256 + threadIdx.x;
    if (i >= total4) return;
    int s = 0;
    #pragma unroll
    for (int k = 0; k < NSEG - 1; k++)
        if (i >= segs.cum4[k + 1]) s = k + 1;
    int j = i - segs.cum4[s];
    float4 v = ((const float4*)segs.src[s])[j];
    __half2* d = (__half2*)segs.dst[s];
    d[2 * j]     = __floats2half2_rn(v.x, v.y);
    d[2 * j + 1] = __floats2half2_rn(v.z, v.w);
}

// ---------------- prep: concat [x|pe] -> xpe16, [W_in|W_pe] -> wcat16, ----
// bcat = b_in + b_pe, statid = identity
__global__ void prep_kernel(const float* __restrict__ x, const float* __restrict__ pe,
                            const float* __restrict__ W_in, const float* __restrict__ W_pe,
                            const float* __restrict__ b_in, const float* __restrict__ b_pe,
                            __half* __restrict__ xpe, __half* __restrict__ wcat,
                            float* __restrict__ bcat, float* __restrict__ statid) {
    const int N1 = BNODES * 34, N2 = HDIM * 34;
    int i = blockIdx.x * 256 + threadIdx.x;
    if (i < N1) {
        int row = i / 34, q = i % 34;
        const float* s; int col;
        if (q < 32) { s = x + (size_t)row * 128 + q * 4; col = q * 4; }
        else        { s = pe + (size_t)row * 8 + (q - 32) * 4; col = 128 + (q - 32) * 4; }
        float4 v = *(const float4*)s;
        __half2* d = (__half2*)(xpe + (size_t)row * 136 + col);
        d[0] = __floats2half2_rn(v.x, v.y);
        d[1] = __floats2half2_rn(v.z, v.w);
        return;
    }
    i -= N1;
    if (i < N2) {
        int row = i / 34, q = i % 34;
        const float* s; int col;
        if (q < 32) { s = W_in + (size_t)row * 128 + q * 4; col = q * 4; }
        else        { s = W_pe + (size_t)row * 8 + (q - 32) * 4; col = 128 + (q - 32) * 4; }
        float4 v = *(const float4*)s;
        __half2* d = (__half2*)(wcat + (size_t)row * 136 + col);
        d[0] = __floats2half2_rn(v.x, v.y);
        d[1] = __floats2half2_rn(v.z, v.w);
        return;
    }
    i -= N2;
    if (i < 64) {
        float4 a = ((const float4*)b_in)[i];
        float4 b = ((const float4*)b_pe)[i];
        ((float4*)bcat)[i] = make_float4(a.x + b.x, a.y + b.y, a.z + b.z, a.w + b.w);
        return;
    }
    i -= 64;
    if (i < 128) {
        ((float4*)statid)[i] = (i < 64) ? make_float4(1.f, 1.f, 1.f, 1.f)
                                        : make_float4(0.f, 0.f, 0.f, 0.f);
    }
}

// ---------------- fp16 GEMM (3-stage cp.async + ldmatrix, BK=64) -----------
// single top-of-iter barrier (3-buffer ring makes trailing sync redundant)
template<int TM>
__device__ __forceinline__ void load_tile_h(
    const __half* __restrict__ A, const __half* __restrict__ W,
    __half (*As)[72], __half (*Bs)[72],
    int bm, int bn, int K, int k0, int tid) {
    #pragma unroll
    for (int i = 0; i < TM / 32; i++) {
        int idx = tid + i * 256;
        int r = idx >> 3, qd = idx & 7;
        const __half* src = A + (size_t)(bm + r) * K + k0 + qd * 8;
        __half* dst = &As[r][qd * 8];
        if (k0 + qd * 8 + 8 <= K) {
            cp_async16(dst, src);
        } else {
            #pragma unroll
            for (int j = 0; j < 8; j++)
                dst[j] = (k0 + qd * 8 + j < K) ? src[j] : __float2half(0.f);
        }
    }
    #pragma unroll
    for (int i = 0; i < 4; i++) {
        int idx = tid + i * 256;
        int r = idx >> 3, qd = idx & 7;
        const __half* src = W + (size_t)(bn + r) * K + k0 + qd * 8;
        __half* dst = &Bs[r][qd * 8];
        if (k0 + qd * 8 + 8 <= K) {
            cp_async16(dst, src);
        } else {
            #pragma unroll
            for (int j = 0; j < 8; j++)
                dst[j] = (k0 + qd * 8 + j < K) ? src[j] : __float2half(0.f);
        }
    }
    CP_COMMIT();
}

template<int TM, int ACT, int RES, bool STATS, int OM>
__global__ __launch_bounds__(256, 2)
void gemm_h_kernel(const __half* __restrict__ A, const __half* __restrict__ W,
                   const float* __restrict__ bias, float* __restrict__ C,
                   __half* __restrict__ C16, const float* __restrict__ stat,
                   int K, int N) {
    constexpr int MT = TM / 32;
    constexpr int RED_OFF = 3 * TM * 72 + 3 * 128 * 72;
    extern __shared__ __half hsm[];
    __half (*As)[72] = (__half(*)[72])hsm;
    __half (*Bs)[72] = (__half(*)[72])(hsm + 3 * TM * 72);

    const int bm = blockIdx.y * TM, bn = blockIdx.x * 128;
    const int tid  = threadIdx.x;
    const int lane = tid & 31;
    const int wid  = tid >> 5;
    const int wm   = wid >> 2;
    const int wn   = wid & 3;
    const int g    = lane >> 2;
    const int tig  = lane & 3;

    const unsigned aBase0 = (unsigned)__cvta_generic_to_shared(&As[0][0]);
    const unsigned bBase0 = aBase0 + 3 * TM * 72 * 2;
    const unsigned aLane = (unsigned)(wm * (TM / 2) + (lane & 15)) * 144
                         + ((lane >> 4) << 4);
    const unsigned bLane = (unsigned)(wn * 32 + ((lane >> 4) << 3) + (lane & 7)) * 144
                         + (((lane >> 3) & 1) << 4);

    float acc[MT][4][4] = {};

    const int KT = (K + 63) >> 6;
    load_tile_h<TM>(A, W, As, Bs, bm, bn, K, 0, tid);
    if (KT > 1)
        load_tile_h<TM>(A, W, As + TM, Bs + 128, bm, bn, K, 64, tid);

    for (int it = 0; it < KT; it++) {
        if (it + 1 < KT) CP_WAIT1(); else CP_WAIT0();
        __syncthreads();       // single barrier per slab
        if (it + 2 < KT) {
            const int nb = (it + 2) % 3;
            load_tile_h<TM>(A, W, As + nb * TM, Bs + nb * 128,
                            bm, bn, K, (it + 2) * 64, tid);
        }

        const unsigned aB = aBase0 + (unsigned)((it % 3) * TM) * 144 + aLane;
        const unsigned bB = bBase0 + (unsigned)((it % 3) * 128) * 144 + bLane;

        #pragma unroll
        for (int ks = 0; ks < 4; ks++) {
            unsigned a[MT][4], b[4][2];
            #pragma unroll
            for (int mt = 0; mt < MT; mt++)
                LDSM4(a[mt][0], a[mt][1], a[mt][2], a[mt][3],
                      aB + mt * (16 * 144) + ks * 32);
            LDSM4(b[0][0], b[0][1], b[1][0], b[1][1], bB + ks * 32);
            LDSM4(b[2][0], b[2][1], b[3][0], b[3][1], bB + 16 * 144 + ks * 32);
            #pragma unroll
            for (int mt = 0; mt < MT; mt++)
                #pragma unroll
                for (int nt = 0; nt < 4; nt++)
                    MMA_F16(acc[mt][nt][0], acc[mt][nt][1],
                            acc[mt][nt][2], acc[mt][nt][3],
                            a[mt][0], a[mt][1], a[mt][2], a[mt][3],
                            b[nt][0], b[nt][1]);
        }
    }

    float cs[4][2], cq[4][2];
    if (STATS) {
        #pragma unroll
        for (int nt = 0; nt < 4; nt++)
            cs[nt][0] = cs[nt][1] = cq[nt][0] = cq[nt][1] = 0.f;
    }

    #pragma unroll
    for (int mt = 0; mt < MT; mt++) {
        const int row = bm + wm * (TM / 2) + mt * 16 + g;
        #pragma unroll
        for (int nt = 0; nt < 4; nt++) {
            const int col = bn + wn * 32 + nt * 8 + 2 * tig;
            float b0 = 0.f, b1 = 0.f;
            if (bias) { b0 = bias[col]; b1 = bias[col + 1]; }
            float A0, A1, C0, C1;
            if (RES == 2) {
                A0 = stat[col]; A1 = stat[col + 1];
                C0 = stat[HDIM + col]; C1 = stat[HDIM + col + 1];
            }
            #pragma unroll
            for (int half_ = 0; half_ < 2; half_++) {
                const int r = row + half_ * 8;
                size_t idx = (size_t)r * N + col;
                float c0 = acc[mt][nt][half_ * 2 + 0] + b0;
                float c1 = acc[mt][nt][half_ * 2 + 1] + b1;
                if (RES == 1) { c0 += C[idx]; c1 += C[idx + 1]; }
                if (RES == 2) {
                    c0 += C[idx] * A0 + C0;
                    c1 += C[idx + 1] * A1 + C1;
                }
                if (ACT == 1) { c0 = gelu_f(c0); c1 = gelu_f(c1); }
                if (OM != 2) { C[idx] = c0; C[idx + 1] = c1; }
                if (OM >= 1)
                    *(__half2*)(C16 + idx) = __floats2half2_rn(c0, c1);
                if (STATS) {
                    cs[nt][0] += c0; cq[nt][0] += c0 * c0;
                    cs[nt][1] += c1; cq[nt][1] += c1 * c1;
                }
            }
        }
    }

    if (STATS) {
        float* sred = (float*)(hsm + RED_OFF);
        #pragma unroll
        for (int nt = 0; nt < 4; nt++)
            #pragma unroll
            for (int j = 0; j < 2; j++) {
                #pragma unroll
                for (int m = 4; m <= 16; m <<= 1) {
                    cs[nt][j] += __shfl_xor_sync(0xffffffffu, cs[nt][j], m);
                    cq[nt][j] += __shfl_xor_sync(0xffffffffu, cq[nt][j], m);
                }
            }
        __syncthreads();   // all warps done with tile smem before sred reuse
        if (g == 0) {
            #pragma unroll
            for (int nt = 0; nt < 4; nt++)
                #pragma unroll
                for (int j = 0; j < 2; j++) {
                    int c = wn * 32 + nt * 8 + 2 * tig + j;
                    sred[wm * 128 + c]       = cs[nt][j];
                    sred[256 + wm * 128 + c] = cq[nt][j];
                }
        }
        __syncthreads();
        if (tid < 128) {
            int c = tid;
            g_psum[blockIdx.y * HDIM + bn + c] = sred[c] + sred[128 + c];
            g_psq [blockIdx.y * HDIM + bn + c] = sred[256 + c] + sred[384 + c];
        }
    }
}

#define GEMM_SMEM_64  ((3 * 64 * 72 + 3 * 128 * 72) * 2 + 512 * 4)
#define GEMM_SMEM_128 ((3 * 128 * 72 + 3 * 128 * 72) * 2)

// ---------------- CSR build: fused count+fill -------------------------------
__global__ void count_fill_kernel(const int* __restrict__ row,
                                  int* __restrict__ cnt,
                                  int* __restrict__ slot) {
    int e = blockIdx.x * 256 + threadIdx.x;
    if (e < NEDGE) {
        int r = row[e];
        int p = atomicAdd(&cnt[r], 1);
        if (p < SLOTCAP) slot[r * SLOTCAP + p] = e;
    }
}

// ---------------- GCN gather -------------------------------------------------
__global__ void gcn_gather_kernel(const __half* __restrict__ t1h,
                                  const int* __restrict__ cnt,
                                  const int* __restrict__ slot,
                                  const int* __restrict__ ecol,
                                  const float* __restrict__ eval,
                                  __half* __restrict__ agg) {
    const int node = blockIdx.x;
    const int f2 = threadIdx.x;
    __shared__ int   scol[64];
    __shared__ float sval[64];
    const int n_e = min(cnt[node], SLOTCAP);
    float a0 = 0.f, a1 = 0.f;
    const __half2* t1h2 = (const __half2*)t1h;
    for (int base = 0; base < n_e; base += 64) {
        int n = min(64, n_e - base);
        if (f2 < n) {
            int e = slot[node * SLOTCAP + base + f2];
            scol[f2] = ecol[e];
            sval[f2] = eval[e];
        }
        __syncthreads();
        for (int j = 0; j < n; j++) {
            float2 v = __half22float2(t1h2[(size_t)scol[j] * 128 + f2]);
            a0 += sval[j] * v.x;
            a1 += sval[j] * v.y;
        }
        __syncthreads();
    }
    ((__half2*)agg)[(size_t)node * 128 + f2] = __floats2half2_rn(a0, a1);
}

// ---------------- BatchNorm -------------------------------------------------
__global__ void bnpre_kernel(float* __restrict__ h, const __half* __restrict__ add,
                             float* __restrict__ psum, float* __restrict__ psq,
                             const float* __restrict__ statPrev) {
    const int f = threadIdx.x;
    const int blk = blockIdx.x;
    const float A = statPrev[f], C = statPrev[HDIM + f];
    float s = 0.f, sq = 0.f;
    size_t base = (size_t)blk * 32 * HDIM + f;
    #pragma unroll 4
    for (int r = 0; r < 32; r++) {
        size_t idx = base + (size_t)r * HDIM;
        float v = h[idx] * A + C + gelu_f(__half2float(add[idx]));
        h[idx] = v;
        s += v;
        sq += v * v;
    }
    psum[blk * HDIM + f] = s;
    psq [blk * HDIM + f] = sq;
}

__global__ void bnstat_kernel(const float* __restrict__ psum,
                              const float* __restrict__ psq,
                              const float* __restrict__ g,
                              const float* __restrict__ b,
                              float* __restrict__ stat, int npart) {
    const int f = blockIdx.x * 128 + threadIdx.x;
    float s = 0.f, sq = 0.f;
    for (int p = 0; p < npart; p++) { s += psum[p * HDIM + f]; sq += psq[p * HDIM + f]; }
    const float mu = s * (1.0f / BNODES);
    const float istd = rsqrtf(sq * (1.0f / BNODES) - mu * mu + 1e-5f);
    const float A = istd * g[f];
    stat[f]        = A;
    stat[HDIM + f] = b[f] - mu * A;
}

__global__ void bnapply_kernel(const float* __restrict__ h, __half* __restrict__ h16,
                               const float* __restrict__ stat) {
    const int cq = threadIdx.x & 63;
    const int ro = threadIdx.x >> 6;
    const float4 Av = *(const float4*)(stat + 4 * cq);
    const float4 Cv = *(const float4*)(stat + HDIM + 4 * cq);
    const float4* h4 = (const float4*)h;
    __half2* o2 = (__half2*)h16;
    const int row0 = blockIdx.x * 32 + ro * 8;
    #pragma unroll
    for (int i = 0; i < 8; i++) {
        size_t idx = (size_t)(row0 + i) * 64 + cq;
        float4 v = h4[idx];
        o2[2 * idx]     = __floats2half2_rn(v.x * Av.x + Cv.x, v.y * Av.y + Cv.y);
        o2[2 * idx + 1] = __floats2half2_rn(v.z * Av.z + Cv.z, v.w * Av.w + Cv.w);
    }
}

// ---------------- fp16 flash attention (3-buffer KV ring) -------------------
#define ATTN_SMEM ((3 * 64 * 56 + 3 * 64 * 56 + 128 * 72) * 2)

__global__ __launch_bounds__(256)
void attn_h_kernel(const __half* __restrict__ qkv, __half* __restrict__ out) {
    extern __shared__ __half hsm[];
    __half (*Kh)[64][56] = (__half(*)[64][56])hsm;
    __half (*Vh)[64][56] = (__half(*)[64][56])(hsm + 3 * 64 * 56);
    __half (*Sh)[72]     = (__half(*)[72])(hsm + 6 * 64 * 56);
    __half* Qs = (__half*)Sh;

    const int qt = blockIdx.x, nh = blockIdx.y, b = blockIdx.z;
    const int tid  = threadIdx.x;
    const int lane = tid & 31;
    const int w    = tid >> 5;
    const int g    = lane >> 2;
    const int tig  = lane & 3;
    const float scale = 0.17677669529663687f;
    const float L2E = 1.4426950408889634f;

    const size_t rowb = (size_t)(b * 1024) * 768 + nh * 32;

    {
        size_t qoff = rowb + (size_t)(qt * 128) * 768;
        #pragma unroll
        for (int i = 0; i < 2; i++) {
            int idx = tid + i * 256;
            int r = idx >> 2, qd = idx & 3;
            cp_async16(Qs + r * 56 + qd * 8, qkv + qoff + (size_t)r * 768 + qd * 8);
        }
        CP_COMMIT();
    }
    {
        int r = tid >> 2, qd = tid & 3;
        cp_async16(&Kh[0][r][qd * 8], qkv + rowb + (size_t)r * 768 + 256 + qd * 8);
        cp_async16(&Vh[0][r][qd * 8], qkv + rowb + (size_t)r * 768 + 512 + qd * 8);
        CP_COMMIT();
    }
    CP_WAIT1();
    __syncthreads();

    unsigned q[2][4];
    {
        unsigned qA = (unsigned)__cvta_generic_to_shared(Qs)
                    + (unsigned)(w * 16 + (lane & 15)) * 112 + ((lane >> 4) << 4);
        LDSM4(q[0][0], q[0][1], q[0][2], q[0][3], qA);
        LDSM4(q[1][0], q[1][1], q[1][2], q[1][3], qA + 32);
    }
    __syncthreads();

    const unsigned kLane = (unsigned)(((lane >> 4) << 3) + (lane & 7)) * 112
                         + (((lane >> 3) & 1) << 4);
    const unsigned pLane = (unsigned)(w * 16 + (lane & 15)) * 144 + ((lane >> 4) << 4);
    const unsigned vLane = (unsigned)((((lane >> 3) & 1) << 3) + (lane & 7)) * 112
                         + ((lane >> 4) << 4);
    const unsigned pBase = (unsigned)__cvta_generic_to_shared(&Sh[0][0]) + pLane;
    const int r0 = w * 16 + g;

    float m0 = -1e30f, m1 = -1e30f, l0 = 0.f, l1 = 0.f;
    float o[4][4] = {};

    for (int kt = 0; kt < 16; kt++) {
        if (kt + 1 < 16) {
            size_t koff = rowb + (size_t)((kt + 1) * 64) * 768;
            int st = (kt + 1) % 3;
            int r = tid >> 2, qd = tid & 3;
            cp_async16(&Kh[st][r][qd * 8], qkv + koff + (size_t)r * 768 + 256 + qd * 8);
            cp_async16(&Vh[st][r][qd * 8], qkv + koff + (size_t)r * 768 + 512 + qd * 8);
            CP_COMMIT();
            CP_WAIT1();
        } else {
            CP_WAIT0();
        }
        __syncthreads();

        const int cb = kt % 3;
        const unsigned kBase = (unsigned)__cvta_generic_to_shared(&Kh[cb][0][0]) + kLane;
        const unsigned vBase = (unsigned)__cvta_generic_to_shared(&Vh[cb][0][0]) + vLane;

        float s[8][4] = {};
        #pragma unroll
        for (int ks = 0; ks < 2; ks++) {
            #pragma unroll
            for (int grp = 0; grp < 4; grp++) {
                unsigned b0, b1, b2, b3;
                LDSM4(b0, b1, b2, b3, kBase + grp * (16 * 112) + ks * 32);
                MMA_F16(s[grp*2  ][0], s[grp*2  ][1], s[grp*2  ][2], s[grp*2  ][3],
                        q[ks][0], q[ks][1], q[ks][2], q[ks][3], b0, b1);
                MMA_F16(s[grp*2+1][0], s[grp*2+1][1], s[grp*2+1][2], s[grp*2+1][3],
                        q[ks][0], q[ks][1], q[ks][2], q[ks][3], b2, b3);
            }
        }

        float rmax0 = -1e30f, rmax1 = -1e30f;
        #pragma unroll
        for (int nt = 0; nt < 8; nt++) {
            s[nt][0] *= scale; s[nt][1] *= scale;
            s[nt][2] *= scale; s[nt][3] *= scale;
            rmax0 = fmaxf(rmax0, fmaxf(s[nt][0], s[nt][1]));
            rmax1 = fmaxf(rmax1, fmaxf(s[nt][2], s[nt][3]));
        }
        rmax0 = fmaxf(rmax0, __shfl_xor_sync(0xffffffffu, rmax0, 1));
        rmax0 = fmaxf(rmax0, __shfl_xor_sync(0xffffffffu, rmax0, 2));
        rmax1 = fmaxf(rmax1, __shfl_xor_sync(0xffffffffu, rmax1, 1));
        rmax1 = fmaxf(rmax1, __shfl_xor_sync(0xffffffffu, rmax1, 2));

        float mn0 = fmaxf(m0, rmax0), mn1 = fmaxf(m1, rmax1);
        float cor0 = __expf(m0 - mn0), cor1 = __expf(m1 - mn1);
        m0 = mn0; m1 = mn1;
        const float mL0 = mn0 * L2E, mL1 = mn1 * L2E;

        float ps0 = 0.f, ps1 = 0.f;
        #pragma unroll
        for (int nt = 0; nt < 8; nt++) {
            __half2 hp0 = h2exp2(__floats2half2_rn(fmaf(s[nt][0], L2E, -mL0),
                                                   fmaf(s[nt][1], L2E, -mL0)));
            __half2 hp1 = h2exp2(__floats2half2_rn(fmaf(s[nt][2], L2E, -mL1),
                                                   fmaf(s[nt][3], L2E, -mL1)));
            int c = nt * 8 + 2 * tig;
            *(__half2*)&Sh[r0    ][c] = hp0;
            *(__half2*)&Sh[r0 + 8][c] = hp1;
            float2 p0 = __half22float2(hp0);
            float2 p1 = __half22float2(hp1);
            ps0 += p0.x + p0.y;
            ps1 += p1.x + p1.y;
        }
        ps0 += __shfl_xor_sync(0xffffffffu, ps0, 1);
        ps0 += __shfl_xor_sync(0xffffffffu, ps0, 2);
        ps1 += __shfl_xor_sync(0xffffffffu, ps1, 1);
        ps1 += __shfl_xor_sync(0xffffffffu, ps1, 2);
        l0 = l0 * cor0 + ps0;
        l1 = l1 * cor1 + ps1;
        #pragma unroll
        for (int nt = 0; nt < 4; nt++) {
            o[nt][0] *= cor0; o[nt][1] *= cor0;
            o[nt][2] *= cor1; o[nt][3] *= cor1;
        }
        __syncwarp();

        #pragma unroll
        for (int ks = 0; ks < 4; ks++) {
            unsigned a0, a1, a2, a3;
            LDSM4(a0, a1, a2, a3, pBase + ks * 32);
            #pragma unroll
            for (int dg = 0; dg < 2; dg++) {
                unsigned v0, v1, v2, v3;
                LDSM4T(v0, v1, v2, v3, vBase + ks * (16 * 112) + dg * 32);
                MMA_F16(o[dg*2  ][0], o[dg*2  ][1], o[dg*2  ][2], o[dg*2  ][3],
                        a0, a1, a2, a3, v0, v1);
                MMA_F16(o[dg*2+1][0], o[dg*2+1][1], o[dg*2+1][2], o[dg*2+1][3],
                        a0, a1, a2, a3, v2, v3);
            }
        }
    }

    const float inv0 = 1.0f / l0, inv1 = 1.0f / l1;
    const int row0 = b * 1024 + qt * 128 + w * 16 + g;
    #pragma unroll
    for (int nt = 0; nt < 4; nt++) {
        const int col = nh * 32 + nt * 8 + 2 * tig;
        size_t i0 = (size_t)row0 * HDIM + col;
        size_t i1 = (size_t)(row0 + 8) * HDIM + col;
        *(__half2*)(out + i0) = __floats2half2_rn(o[nt][0] * inv0, o[nt][1] * inv0);
        *(__half2*)(out + i1) = __floats2half2_rn(o[nt][2] * inv1, o[nt][3] * inv1);
    }
}

// ---------------- head final ------------------------------------------------
__global__ void head_final_kernel(const float* __restrict__ t, const float* __restrict__ w,
                                  const float* __restrict__ b, float* __restrict__ out) {
    int row = blockIdx.x * 8 + (threadIdx.x >> 5);
    int lane = threadIdx.x & 31;
    float acc = 0.f;
    #pragma unroll
    for (int i = lane; i < 128; i += 32)
        acc += t[(size_t)row * 128 + i] * w[i];
    #pragma unroll
    for (int ofs = 16; ofs; ofs >>= 1)
        acc += __shfl_xor_sync(0xffffffffu, acc, ofs);
    if (lane == 0)
        out[row] = 1.0f / (1.0f + expf(-(acc + b[0])));
}

// ---------------- host orchestration ----------------------------------------
extern "C" void kernel_launch(void* const* d_in, const int* in_sizes, int n_in,
                              void* d_out, int out_size) {
    const float* x        = (const float*)d_in[0];
    const int*   erow     = (const int*)  d_in[1];
    const int*   ecol     = (const int*)  d_in[2];
    const float* eval     = (const float*)d_in[3];
    const float* pe       = (const float*)d_in[4];
    const float* W_in     = (const float*)d_in[5];
    const float* b_in     = (const float*)d_in[6];
    const float* W_pe     = (const float*)d_in[7];
    const float* b_pe     = (const float*)d_in[8];
    const float* gcn_W    = (const float*)d_in[9];
    const float* ain_W    = (const float*)d_in[10];
    const float* ain_b    = (const float*)d_in[11];
    const float* aout_W   = (const float*)d_in[12];
    const float* aout_b   = (const float*)d_in[13];
    const float* bn_g     = (const float*)d_in[14];
    const float* bn_b     = (const float*)d_in[15];
    const float* ffn_W1   = (const float*)d_in[16];
    const float* ffn_b1   = (const float*)d_in[17];
    const float* ffn_W2   = (const float*)d_in[18];
    const float* ffn_b2   = (const float*)d_in[19];
    const float* head_W1  = (const float*)d_in[20];
    const float* head_b1  = (const float*)d_in[21];
    const float* head_W2  = (const float*)d_in[22];
    const float* head_b2  = (const float*)d_in[23];

    float *h, *t1, *psum, *psq, *stat, *statid, *bcat;
    __half *w16, *xpe16, *wcat16, *h16, *t1h, *t2h;
    int *cnt, *slot;
    cudaGetSymbolAddress((void**)&h,      g_h);
    cudaGetSymbolAddress((void**)&t1,     g_t1);
    cudaGetSymbolAddress((void**)&psum,   g_psum);
    cudaGetSymbolAddress((void**)&psq,    g_psq);
    cudaGetSymbolAddress((void**)&stat,   g_stat);
    cudaGetSymbolAddress((void**)&statid, g_statid);
    cudaGetSymbolAddress((void**)&bcat,   g_bcat);
    cudaGetSymbolAddress((void**)&cnt,    g_cnt);
    cudaGetSymbolAddress((void**)&slot,   g_slot);
    cudaGetSymbolAddress((void**)&w16,    g_w16);
    cudaGetSymbolAddress((void**)&xpe16,  g_xpe16);
    cudaGetSymbolAddress((void**)&wcat16, g_wcat16);
    cudaGetSymbolAddress((void**)&h16,    g_h16);
    cudaGetSymbolAddress((void**)&t1h,    g_t1h);
    cudaGetSymbolAddress((void**)&t2h,    g_t2h);

    cudaFuncSetAttribute(attn_h_kernel,
                         cudaFuncAttributeMaxDynamicSharedMemorySize, ATTN_SMEM);
    cudaFuncSetAttribute(gemm_h_kernel<64, 0, 0, false, 1>,
                         cudaFuncAttributeMaxDynamicSharedMemorySize, GEMM_SMEM_64);
    cudaFuncSetAttribute(gemm_h_kernel<64, 0, 0, false, 2>,
                         cudaFuncAttributeMaxDynamicSharedMemorySize, GEMM_SMEM_64);
    cudaFuncSetAttribute(gemm_h_kernel<64, 0, 2, true, 0>,
                         cudaFuncAttributeMaxDynamicSharedMemorySize, GEMM_SMEM_64);
    cudaFuncSetAttribute(gemm_h_kernel<64, 1, 0, false, 0>,
                         cudaFuncAttributeMaxDynamicSharedMemorySize, GEMM_SMEM_64);
    cudaFuncSetAttribute(gemm_h_kernel<128, 0, 0, false, 2>,
                         cudaFuncAttributeMaxDynamicSharedMemorySize, GEMM_SMEM_128);
    cudaFuncSetAttribute(gemm_h_kernel<128, 1, 0, false, 2>,
                         cudaFuncAttributeMaxDynamicSharedMemorySize, GEMM_SMEM_128);

    // prep: xpe concat + wcat concat + bias sum + identity stat
    {
        int total = BNODES * 34 + HDIM * 34 + 64 + 128;
        prep_kernel<<<(total + 255) / 256, 256>>>(x, pe, W_in, W_pe, b_in, b_pe,
                                                  xpe16, wcat16, bcat, statid);
    }
    // weight conversion
    {
        ConvSegs segs;
        const float* srcs[NSEG] = {gcn_W, ain_W, aout_W, ffn_W1, ffn_W2, head_W1};
        __half* dsts[NSEG] = {w16 + OFF_GCN, w16 + OFF_AIN, w16 + OFF_AOUT,
                              w16 + OFF_FFN1, w16 + OFF_FFN2, w16 + OFF_HW1};
        int cnts[NSEG] = {NLAYER * HDIM * HDIM, NLAYER * 768 * HDIM,
                          NLAYER * HDIM * HDIM, NLAYER * 1024 * HDIM,
                          NLAYER * HDIM * 1024, 128 * HDIM};
        int cum = 0;
        for (int i = 0; i < NSEG; i++) {
            segs.src[i] = srcs[i];
            segs.dst[i] = dsts[i];
            segs.cum4[i] = cum;
            cum += cnts[i] / 4;
        }
        segs.cum4[NSEG] = cum;
        f2h_multi_kernel<<<(cum + 255) / 256, 256>>>(segs, cum);
    }

    // CSR build
    cudaMemsetAsync(cnt, 0, BNODES * sizeof(int));
    count_fill_kernel<<<NEDGE / 256, 256>>>(erow, cnt, slot);

    const dim3 g256 (2, BNODES / 64);
    const dim3 g768 (6, BNODES / 128);
    const dim3 g1024(8, BNODES / 128);
    const dim3 g128 (1, BNODES / 64);

    // merged input projection: h = [x|pe] @ [W_in|W_pe]^T + (b_in+b_pe), +h16
    gemm_h_kernel<64, 0, 0, false, 1><<<g256, 256, GEMM_SMEM_64>>>(
        xpe16, wcat16, bcat, h, h16, nullptr, 136, HDIM);

    for (int l = 0; l < NLAYER; l++) {
        const float* statPrev = (l == 0) ? statid : stat;
        // ---- local GCN ----
        gemm_h_kernel<64, 0, 0, false, 2><<<g256, 256, GEMM_SMEM_64>>>(
            h16, w16 + OFF_GCN + (size_t)l * HDIM * HDIM, nullptr,
            nullptr, t1h, nullptr, HDIM, HDIM);
        gcn_gather_kernel<<<BNODES, 128>>>(t1h, cnt, slot, ecol, eval, t2h);
        bnpre_kernel<<<256, 256>>>(h, t2h, psum, psq, statPrev);
        bnstat_kernel<<<2, 128>>>(psum, psq, bn_g + l * 3 * HDIM,
                                  bn_b + l * 3 * HDIM, stat, 256);
        bnapply_kernel<<<256, 256>>>(h, h16, stat);
        // ---- global attention ----
        gemm_h_kernel<128, 0, 0, false, 2><<<g768, 256, GEMM_SMEM_128>>>(
            h16, w16 + OFF_AIN + (size_t)l * 768 * HDIM, ain_b + l * 768,
            nullptr, t1h, nullptr, HDIM, 768);
        attn_h_kernel<<<dim3(8, 8, 8), 256, ATTN_SMEM>>>(t1h, t2h);
        gemm_h_kernel<64, 0, 2, true, 0><<<g256, 256, GEMM_SMEM_64>>>(
            t2h, w16 + OFF_AOUT + (size_t)l * HDIM * HDIM, aout_b + l * HDIM,
            h, nullptr, stat, HDIM, HDIM);
        bnstat_kernel<<<2, 128>>>(psum, psq, bn_g + l * 3 * HDIM + HDIM,
                                  bn_b + l * 3 * HDIM + HDIM, stat, 128);
        bnapply_kernel<<<256, 256>>>(h, h16, stat);
        // ---- FFN ----
        gemm_h_kernel<128, 1, 0, false, 2><<<g1024, 256, GEMM_SMEM_128>>>(
            h16, w16 + OFF_FFN1 + (size_t)l * 1024 * HDIM, ffn_b1 + l * 1024,
            nullptr, t1h, nullptr, HDIM, 1024);
        gemm_h_kernel<64, 0, 2, true, 0><<<g256, 256, GEMM_SMEM_64>>>(
            t1h, w16 + OFF_FFN2 + (size_t)l * HDIM * 1024, ffn_b2 + l * HDIM,
            h, nullptr, stat, 1024, HDIM);
        bnstat_kernel<<<2, 128>>>(psum, psq, bn_g + l * 3 * HDIM + 2 * HDIM,
                                  bn_b + l * 3 * HDIM + 2 * HDIM, stat, 128);
        bnapply_kernel<<<256, 256>>>(h, h16, stat);
    }

    // ---- head ----
    gemm_h_kernel<64, 1, 0, false, 0><<<g128, 256, GEMM_SMEM_64>>>(
        h16, w16 + OFF_HW1, head_b1, t1, nullptr, nullptr, HDIM, 128);
    head_final_kernel<<<BNODES / 8, 256>>>(t1, head_W2, head_b2, (float*)d_out);
}

// round 15
// speedup vs baseline: 1.0000x; 1.0000x over previous
#include <cuda_runtime.h>
#include <cuda_fp16.h>
#include <math.h>

#define BNODES 8192
#define HDIM   256
#define NEDGE  131072
#define NLAYER 4
#define SLOTCAP 128
#define KPAD   192

// fp32 scratch
__device__ float g_h [BNODES * HDIM];
__device__ float g_t1[BNODES * HDIM];
__device__ int   g_cnt[BNODES];
__device__ int   g_slot[BNODES * SLOTCAP];
__device__ float g_psum[256 * HDIM];
__device__ float g_psq [256 * HDIM];
__device__ float g_stat[2 * HDIM];
__device__ float g_statid[2 * HDIM];
__device__ float g_bcat[HDIM];
// fp16 scratch
__device__ __half g_w16[3442688];
__device__ __half g_xpe16[BNODES * KPAD];
__device__ __half g_wcat16[HDIM * KPAD];
__device__ __half g_h16[BNODES * HDIM];
__device__ __half g_t1h[BNODES * 1024];
__device__ __half g_t2h[BNODES * HDIM];

#define OFF_GCN  0
#define OFF_AIN  262144
#define OFF_AOUT 1048576
#define OFF_FFN1 1310720
#define OFF_FFN2 2359296
#define OFF_HW1  3407872

__device__ __forceinline__ float gelu_f(float x) {
    return 0.5f * x * (1.0f + erff(x * 0.70710678118654752f));
}

__device__ __forceinline__ void cp_async16(void* smem_dst, const void* gmem_src) {
    unsigned s = (unsigned)__cvta_generic_to_shared(smem_dst);
    asm volatile("cp.async.cg.shared.global [%0], [%1], 16;\n" :: "r"(s), "l"(gmem_src));
}
#define CP_COMMIT() asm volatile("cp.async.commit_group;\n" ::: "memory")
#define CP_WAIT1()  asm volatile("cp.async.wait_group 1;\n" ::: "memory")
#define CP_WAIT0()  asm volatile("cp.async.wait_group 0;\n" ::: "memory")

#define MMA_F16(c0,c1,c2,c3, a0,a1,a2,a3, b0,b1)                           \
    asm volatile(                                                          \
        "mma.sync.aligned.m16n8k16.row.col.f32.f16.f16.f32 "               \
        "{%0,%1,%2,%3}, {%4,%5,%6,%7}, {%8,%9}, {%0,%1,%2,%3};\n"          \
        : "+f"(c0), "+f"(c1), "+f"(c2), "+f"(c3)                            \
        : "r"(a0), "r"(a1), "r"(a2), "r"(a3), "r"(b0), "r"(b1))

#define LDSM4(r0,r1,r2,r3, addr)                                            \
    asm volatile("ldmatrix.sync.aligned.m8n8.x4.shared.b16 {%0,%1,%2,%3}, [%4];" \
        : "=r"(r0), "=r"(r1), "=r"(r2), "=r"(r3) : "r"(addr))

#define LDSM4T(r0,r1,r2,r3, addr)                                           \
    asm volatile("ldmatrix.sync.aligned.m8n8.x4.trans.shared.b16 {%0,%1,%2,%3}, [%4];" \
        : "=r"(r0), "=r"(r1), "=r"(r2), "=r"(r3) : "r"(addr))

// ---------------- batched fp32 -> fp16 convert (weights) -------------------
#define NSEG 6
struct ConvSegs {
    const float* src[NSEG];
    __half*      dst[NSEG];
    int          cum4[NSEG + 1];
};

__global__ void f2h_multi_kernel(ConvSegs segs, int total4) {
    int i = blockIdx.x * 256 + threadIdx.x;
    if (i >= total4) return;
    int s = 0;
    #pragma unroll
    for (int k = 0; k < NSEG - 1; k++)
        if (i >= segs.cum4[k + 1]) s = k + 1;
    int j = i - segs.cum4[s];
    float4 v = ((const float4*)segs.src[s])[j];
    __half2* d = (__half2*)segs.dst[s];
    d[2 * j]     = __floats2half2_rn(v.x, v.y);
    d[2 * j + 1] = __floats2half2_rn(v.z, v.w);
}

// ---------------- prep: [x|pe|0pad] -> xpe16 (stride 192), same for wcat ---
__global__ void prep_kernel(const float* __restrict__ x, const float* __restrict__ pe,
                            const float* __restrict__ W_in, const float* __restrict__ W_pe,
                            const float* __restrict__ b_in, const float* __restrict__ b_pe,
                            __half* __restrict__ xpe, __half* __restrict__ wcat,
                            float* __restrict__ bcat, float* __restrict__ statid) {
    const int QR = KPAD / 4;               // 48 quads per row
    const int N1 = BNODES * QR, N2 = HDIM * QR;
    int i = blockIdx.x * 256 + threadIdx.x;
    if (i < N1) {
        int row = i / QR, q = i % QR;
        float4 v = make_float4(0.f, 0.f, 0.f, 0.f);
        if (q < 32)       v = *(const float4*)(x + (size_t)row * 128 + q * 4);
        else if (q < 34)  v = *(const float4*)(pe + (size_t)row * 8 + (q - 32) * 4);
        __half2* d = (__half2*)(xpe + (size_t)row * KPAD + q * 4);
        d[0] = __floats2half2_rn(v.x, v.y);
        d[1] = __floats2half2_rn(v.z, v.w);
        return;
    }
    i -= N1;
    if (i < N2) {
        int row = i / QR, q = i % QR;
        float4 v = make_float4(0.f, 0.f, 0.f, 0.f);
        if (q < 32)       v = *(const float4*)(W_in + (size_t)row * 128 + q * 4);
        else if (q < 34)  v = *(const float4*)(W_pe + (size_t)row * 8 + (q - 32) * 4);
        __half2* d = (__half2*)(wcat + (size_t)row * KPAD + q * 4);
        d[0] = __floats2half2_rn(v.x, v.y);
        d[1] = __floats2half2_rn(v.z, v.w);
        return;
    }
    i -= N2;
    if (i < 64) {
        float4 a = ((const float4*)b_in)[i];
        float4 b = ((const float4*)b_pe)[i];
        ((float4*)bcat)[i] = make_float4(a.x + b.x, a.y + b.y, a.z + b.z, a.w + b.w);
        return;
    }
    i -= 64;
    if (i < 128) {
        ((float4*)statid)[i] = (i < 64) ? make_float4(1.f, 1.f, 1.f, 1.f)
                                        : make_float4(0.f, 0.f, 0.f, 0.f);
    }
}

// ---------------- fp16 GEMM (3-stage cp.async + ldmatrix, BK=64) -----------
// two barriers per slab (proven config)
template<int TM>
__device__ __forceinline__ void load_tile_h(
    const __half* __restrict__ A, const __half* __restrict__ W,
    __half (*As)[72], __half (*Bs)[72],
    int bm, int bn, int K, int k0, int tid) {
    #pragma unroll
    for (int i = 0; i < TM / 32; i++) {
        int idx = tid + i * 256;
        int r = idx >> 3, qd = idx & 7;
        const __half* src = A + (size_t)(bm + r) * K + k0 + qd * 8;
        __half* dst = &As[r][qd * 8];
        if (k0 + qd * 8 + 8 <= K) {
            cp_async16(dst, src);
        } else {
            #pragma unroll
            for (int j = 0; j < 8; j++)
                dst[j] = (k0 + qd * 8 + j < K) ? src[j] : __float2half(0.f);
        }
    }
    #pragma unroll
    for (int i = 0; i < 4; i++) {
        int idx = tid + i * 256;
        int r = idx >> 3, qd = idx & 7;
        const __half* src = W + (size_t)(bn + r) * K + k0 + qd * 8;
        __half* dst = &Bs[r][qd * 8];
        if (k0 + qd * 8 + 8 <= K) {
            cp_async16(dst, src);
        } else {
            #pragma unroll
            for (int j = 0; j < 8; j++)
                dst[j] = (k0 + qd * 8 + j < K) ? src[j] : __float2half(0.f);
        }
    }
    CP_COMMIT();
}

template<int TM, int ACT, int RES, bool STATS, int OM>
__global__ __launch_bounds__(256, 2)
void gemm_h_kernel(const __half* __restrict__ A, const __half* __restrict__ W,
                   const float* __restrict__ bias, float* __restrict__ C,
                   __half* __restrict__ C16, const float* __restrict__ stat,
                   int K, int N) {
    constexpr int MT = TM / 32;
    constexpr int RED_OFF = 3 * TM * 72 + 3 * 128 * 72;
    extern __shared__ __half hsm[];
    __half (*As)[72] = (__half(*)[72])hsm;
    __half (*Bs)[72] = (__half(*)[72])(hsm + 3 * TM * 72);

    const int bm = blockIdx.y * TM, bn = blockIdx.x * 128;
    const int tid  = threadIdx.x;
    const int lane = tid & 31;
    const int wid  = tid >> 5;
    const int wm   = wid >> 2;
    const int wn   = wid & 3;
    const int g    = lane >> 2;
    const int tig  = lane & 3;

    const unsigned aBase0 = (unsigned)__cvta_generic_to_shared(&As[0][0]);
    const unsigned bBase0 = aBase0 + 3 * TM * 72 * 2;
    const unsigned aLane = (unsigned)(wm * (TM / 2) + (lane & 15)) * 144
                         + ((lane >> 4) << 4);
    const unsigned bLane = (unsigned)(wn * 32 + ((lane >> 4) << 3) + (lane & 7)) * 144
                         + (((lane >> 3) & 1) << 4);

    float acc[MT][4][4] = {};

    const int KT = (K + 63) >> 6;
    load_tile_h<TM>(A, W, As, Bs, bm, bn, K, 0, tid);
    if (KT > 1)
        load_tile_h<TM>(A, W, As + TM, Bs + 128, bm, bn, K, 64, tid);

    for (int it = 0; it < KT; it++) {
        if (it + 1 < KT) CP_WAIT1(); else CP_WAIT0();
        __syncthreads();
        if (it + 2 < KT) {
            const int nb = (it + 2) % 3;
            load_tile_h<TM>(A, W, As + nb * TM, Bs + nb * 128,
                            bm, bn, K, (it + 2) * 64, tid);
        }

        const unsigned aB = aBase0 + (unsigned)((it % 3) * TM) * 144 + aLane;
        const unsigned bB = bBase0 + (unsigned)((it % 3) * 128) * 144 + bLane;

        #pragma unroll
        for (int ks = 0; ks < 4; ks++) {
            unsigned a[MT][4], b[4][2];
            #pragma unroll
            for (int mt = 0; mt < MT; mt++)
                LDSM4(a[mt][0], a[mt][1], a[mt][2], a[mt][3],
                      aB + mt * (16 * 144) + ks * 32);
            LDSM4(b[0][0], b[0][1], b[1][0], b[1][1], bB + ks * 32);
            LDSM4(b[2][0], b[2][1], b[3][0], b[3][1], bB + 16 * 144 + ks * 32);
            #pragma unroll
            for (int mt = 0; mt < MT; mt++)
                #pragma unroll
                for (int nt = 0; nt < 4; nt++)
                    MMA_F16(acc[mt][nt][0], acc[mt][nt][1],
                            acc[mt][nt][2], acc[mt][nt][3],
                            a[mt][0], a[mt][1], a[mt][2], a[mt][3],
                            b[nt][0], b[nt][1]);
        }
        __syncthreads();
    }

    float cs[4][2], cq[4][2];
    if (STATS) {
        #pragma unroll
        for (int nt = 0; nt < 4; nt++)
            cs[nt][0] = cs[nt][1] = cq[nt][0] = cq[nt][1] = 0.f;
    }

    #pragma unroll
    for (int mt = 0; mt < MT; mt++) {
        const int row = bm + wm * (TM / 2) + mt * 16 + g;
        #pragma unroll
        for (int nt = 0; nt < 4; nt++) {
            const int col = bn + wn * 32 + nt * 8 + 2 * tig;
            float b0 = 0.f, b1 = 0.f;
            if (bias) { b0 = bias[col]; b1 = bias[col + 1]; }
            float A0, A1, C0, C1;
            if (RES == 2) {
                A0 = stat[col]; A1 = stat[col + 1];
                C0 = stat[HDIM + col]; C1 = stat[HDIM + col + 1];
            }
            #pragma unroll
            for (int half_ = 0; half_ < 2; half_++) {
                const int r = row + half_ * 8;
                size_t idx = (size_t)r * N + col;
                float c0 = acc[mt][nt][half_ * 2 + 0] + b0;
                float c1 = acc[mt][nt][half_ * 2 + 1] + b1;
                if (RES == 1) { c0 += C[idx]; c1 += C[idx + 1]; }
                if (RES == 2) {
                    c0 += C[idx] * A0 + C0;
                    c1 += C[idx + 1] * A1 + C1;
                }
                if (ACT == 1) { c0 = gelu_f(c0); c1 = gelu_f(c1); }
                if (OM != 2) { C[idx] = c0; C[idx + 1] = c1; }
                if (OM >= 1)
                    *(__half2*)(C16 + idx) = __floats2half2_rn(c0, c1);
                if (STATS) {
                    cs[nt][0] += c0; cq[nt][0] += c0 * c0;
                    cs[nt][1] += c1; cq[nt][1] += c1 * c1;
                }
            }
        }
    }

    if (STATS) {
        float* sred = (float*)(hsm + RED_OFF);
        #pragma unroll
        for (int nt = 0; nt < 4; nt++)
            #pragma unroll
            for (int j = 0; j < 2; j++) {
                #pragma unroll
                for (int m = 4; m <= 16; m <<= 1) {
                    cs[nt][j] += __shfl_xor_sync(0xffffffffu, cs[nt][j], m);
                    cq[nt][j] += __shfl_xor_sync(0xffffffffu, cq[nt][j], m);
                }
            }
        if (g == 0) {
            #pragma unroll
            for (int nt = 0; nt < 4; nt++)
                #pragma unroll
                for (int j = 0; j < 2; j++) {
                    int c = wn * 32 + nt * 8 + 2 * tig + j;
                    sred[wm * 128 + c]       = cs[nt][j];
                    sred[256 + wm * 128 + c] = cq[nt][j];
                }
        }
        __syncthreads();
        if (tid < 128) {
            int c = tid;
            g_psum[blockIdx.y * HDIM + bn + c] = sred[c] + sred[128 + c];
            g_psq [blockIdx.y * HDIM + bn + c] = sred[256 + c] + sred[384 + c];
        }
    }
}

#define GEMM_SMEM_64  ((3 * 64 * 72 + 3 * 128 * 72) * 2 + 512 * 4)
#define GEMM_SMEM_128 ((3 * 128 * 72 + 3 * 128 * 72) * 2)

// ---------------- CSR build: fused count+fill -------------------------------
__global__ void count_fill_kernel(const int* __restrict__ row,
                                  int* __restrict__ cnt,
                                  int* __restrict__ slot) {
    int e = blockIdx.x * 256 + threadIdx.x;
    if (e < NEDGE) {
        int r = row[e];
        int p = atomicAdd(&cnt[r], 1);
        if (p < SLOTCAP) slot[r * SLOTCAP + p] = e;
    }
}

// ---------------- GCN gather -------------------------------------------------
__global__ void gcn_gather_kernel(const __half* __restrict__ t1h,
                                  const int* __restrict__ cnt,
                                  const int* __restrict__ slot,
                                  const int* __restrict__ ecol,
                                  const float* __restrict__ eval,
                                  __half* __restrict__ agg) {
    const int node = blockIdx.x;
    const int f2 = threadIdx.x;
    __shared__ int   scol[64];
    __shared__ float sval[64];
    const int n_e = min(cnt[node], SLOTCAP);
    float a0 = 0.f, a1 = 0.f;
    const __half2* t1h2 = (const __half2*)t1h;
    for (int base = 0; base < n_e; base += 64) {
        int n = min(64, n_e - base);
        if (f2 < n) {
            int e = slot[node * SLOTCAP + base + f2];
            scol[f2] = ecol[e];
            sval[f2] = eval[e];
        }
        __syncthreads();
        for (int j = 0; j < n; j++) {
            float2 v = __half22float2(t1h2[(size_t)scol[j] * 128 + f2]);
            a0 += sval[j] * v.x;
            a1 += sval[j] * v.y;
        }
        __syncthreads();
    }
    ((__half2*)agg)[(size_t)node * 128 + f2] = __floats2half2_rn(a0, a1);
}

// ---------------- BatchNorm -------------------------------------------------
__global__ void bnpre_kernel(float* __restrict__ h, const __half* __restrict__ add,
                             float* __restrict__ psum, float* __restrict__ psq,
                             const float* __restrict__ statPrev) {
    const int f = threadIdx.x;
    const int blk = blockIdx.x;
    const float A = statPrev[f], C = statPrev[HDIM + f];
    float s = 0.f, sq = 0.f;
    size_t base = (size_t)blk * 32 * HDIM + f;
    #pragma unroll 4
    for (int r = 0; r < 32; r++) {
        size_t idx = base + (size_t)r * HDIM;
        float v = h[idx] * A + C + gelu_f(__half2float(add[idx]));
        h[idx] = v;
        s += v;
        sq += v * v;
    }
    psum[blk * HDIM + f] = s;
    psq [blk * HDIM + f] = sq;
}

__global__ void bnstat_kernel(const float* __restrict__ psum,
                              const float* __restrict__ psq,
                              const float* __restrict__ g,
                              const float* __restrict__ b,
                              float* __restrict__ stat, int npart) {
    const int f = blockIdx.x * 128 + threadIdx.x;
    float s = 0.f, sq = 0.f;
    for (int p = 0; p < npart; p++) { s += psum[p * HDIM + f]; sq += psq[p * HDIM + f]; }
    const float mu = s * (1.0f / BNODES);
    const float istd = rsqrtf(sq * (1.0f / BNODES) - mu * mu + 1e-5f);
    const float A = istd * g[f];
    stat[f]        = A;
    stat[HDIM + f] = b[f] - mu * A;
}

__global__ void bnapply_kernel(const float* __restrict__ h, __half* __restrict__ h16,
                               const float* __restrict__ stat) {
    const int cq = threadIdx.x & 63;
    const int ro = threadIdx.x >> 6;
    const float4 Av = *(const float4*)(stat + 4 * cq);
    const float4 Cv = *(const float4*)(stat + HDIM + 4 * cq);
    const float4* h4 = (const float4*)h;
    __half2* o2 = (__half2*)h16;
    const int row0 = blockIdx.x * 32 + ro * 8;
    #pragma unroll
    for (int i = 0; i < 8; i++) {
        size_t idx = (size_t)(row0 + i) * 64 + cq;
        float4 v = h4[idx];
        o2[2 * idx]     = __floats2half2_rn(v.x * Av.x + Cv.x, v.y * Av.y + Cv.y);
        o2[2 * idx + 1] = __floats2half2_rn(v.z * Av.z + Cv.z, v.w * Av.w + Cv.w);
    }
}

// ---------------- fp16 flash attention (3-buffer KV ring) -------------------
#define ATTN_SMEM ((3 * 64 * 56 + 3 * 64 * 56 + 128 * 72) * 2)

__global__ __launch_bounds__(256)
void attn_h_kernel(const __half* __restrict__ qkv, __half* __restrict__ out) {
    extern __shared__ __half hsm[];
    __half (*Kh)[64][56] = (__half(*)[64][56])hsm;
    __half (*Vh)[64][56] = (__half(*)[64][56])(hsm + 3 * 64 * 56);
    __half (*Sh)[72]     = (__half(*)[72])(hsm + 6 * 64 * 56);
    __half* Qs = (__half*)Sh;

    const int qt = blockIdx.x, nh = blockIdx.y, b = blockIdx.z;
    const int tid  = threadIdx.x;
    const int lane = tid & 31;
    const int w    = tid >> 5;
    const int g    = lane >> 2;
    const int tig  = lane & 3;
    const float scale = 0.17677669529663687f;
    const float L2E = 1.4426950408889634f;

    const size_t rowb = (size_t)(b * 1024) * 768 + nh * 32;

    {
        size_t qoff = rowb + (size_t)(qt * 128) * 768;
        #pragma unroll
        for (int i = 0; i < 2; i++) {
            int idx = tid + i * 256;
            int r = idx >> 2, qd = idx & 3;
            cp_async16(Qs + r * 56 + qd * 8, qkv + qoff + (size_t)r * 768 + qd * 8);
        }
        CP_COMMIT();
    }
    {
        int r = tid >> 2, qd = tid & 3;
        cp_async16(&Kh[0][r][qd * 8], qkv + rowb + (size_t)r * 768 + 256 + qd * 8);
        cp_async16(&Vh[0][r][qd * 8], qkv + rowb + (size_t)r * 768 + 512 + qd * 8);
        CP_COMMIT();
    }
    CP_WAIT1();
    __syncthreads();

    unsigned q[2][4];
    {
        unsigned qA = (unsigned)__cvta_generic_to_shared(Qs)
                    + (unsigned)(w * 16 + (lane & 15)) * 112 + ((lane >> 4) << 4);
        LDSM4(q[0][0], q[0][1], q[0][2], q[0][3], qA);
        LDSM4(q[1][0], q[1][1], q[1][2], q[1][3], qA + 32);
    }
    __syncthreads();

    const unsigned kLane = (unsigned)(((lane >> 4) << 3) + (lane & 7)) * 112
                         + (((lane >> 3) & 1) << 4);
    const unsigned pLane = (unsigned)(w * 16 + (lane & 15)) * 144 + ((lane >> 4) << 4);
    const unsigned vLane = (unsigned)((((lane >> 3) & 1) << 3) + (lane & 7)) * 112
                         + ((lane >> 4) << 4);
    const unsigned pBase = (unsigned)__cvta_generic_to_shared(&Sh[0][0]) + pLane;
    const int r0 = w * 16 + g;

    float m0 = -1e30f, m1 = -1e30f, l0 = 0.f, l1 = 0.f;
    float o[4][4] = {};

    for (int kt = 0; kt < 16; kt++) {
        if (kt + 1 < 16) {
            size_t koff = rowb + (size_t)((kt + 1) * 64) * 768;
            int st = (kt + 1) % 3;
            int r = tid >> 2, qd = tid & 3;
            cp_async16(&Kh[st][r][qd * 8], qkv + koff + (size_t)r * 768 + 256 + qd * 8);
            cp_async16(&Vh[st][r][qd * 8], qkv + koff + (size_t)r * 768 + 512 + qd * 8);
            CP_COMMIT();
            CP_WAIT1();
        } else {
            CP_WAIT0();
        }
        __syncthreads();

        const int cb = kt % 3;
        const unsigned kBase = (unsigned)__cvta_generic_to_shared(&Kh[cb][0][0]) + kLane;
        const unsigned vBase = (unsigned)__cvta_generic_to_shared(&Vh[cb][0][0]) + vLane;

        float s[8][4] = {};
        #pragma unroll
        for (int ks = 0; ks < 2; ks++) {
            #pragma unroll
            for (int grp = 0; grp < 4; grp++) {
                unsigned b0, b1, b2, b3;
                LDSM4(b0, b1, b2, b3, kBase + grp * (16 * 112) + ks * 32);
                MMA_F16(s[grp*2  ][0], s[grp*2  ][1], s[grp*2  ][2], s[grp*2  ][3],
                        q[ks][0], q[ks][1], q[ks][2], q[ks][3], b0, b1);
                MMA_F16(s[grp*2+1][0], s[grp*2+1][1], s[grp*2+1][2], s[grp*2+1][3],
                        q[ks][0], q[ks][1], q[ks][2], q[ks][3], b2, b3);
            }
        }

        float rmax0 = -1e30f, rmax1 = -1e30f;
        #pragma unroll
        for (int nt = 0; nt < 8; nt++) {
            s[nt][0] *= scale; s[nt][1] *= scale;
            s[nt][2] *= scale; s[nt][3] *= scale;
            rmax0 = fmaxf(rmax0, fmaxf(s[nt][0], s[nt][1]));
            rmax1 = fmaxf(rmax1, fmaxf(s[nt][2], s[nt][3]));
        }
        rmax0 = fmaxf(rmax0, __shfl_xor_sync(0xffffffffu, rmax0, 1));
        rmax0 = fmaxf(rmax0, __shfl_xor_sync(0xffffffffu, rmax0, 2));
        rmax1 = fmaxf(rmax1, __shfl_xor_sync(0xffffffffu, rmax1, 1));
        rmax1 = fmaxf(rmax1, __shfl_xor_sync(0xffffffffu, rmax1, 2));

        float mn0 = fmaxf(m0, rmax0), mn1 = fmaxf(m1, rmax1);
        float cor0 = __expf(m0 - mn0), cor1 = __expf(m1 - mn1);
        m0 = mn0; m1 = mn1;
        const float mL0 = mn0 * L2E, mL1 = mn1 * L2E;

        float ps0 = 0.f, ps1 = 0.f;
        #pragma unroll
        for (int nt = 0; nt < 8; nt++) {
            __half2 hp0 = h2exp2(__floats2half2_rn(fmaf(s[nt][0], L2E, -mL0),
                                                   fmaf(s[nt][1], L2E, -mL0)));
            __half2 hp1 = h2exp2(__floats2half2_rn(fmaf(s[nt][2], L2E, -mL1),
                                                   fmaf(s[nt][3], L2E, -mL1)));
            int c = nt * 8 + 2 * tig;
            *(__half2*)&Sh[r0    ][c] = hp0;
            *(__half2*)&Sh[r0 + 8][c] = hp1;
            float2 p0 = __half22float2(hp0);
            float2 p1 = __half22float2(hp1);
            ps0 += p0.x + p0.y;
            ps1 += p1.x + p1.y;
        }
        ps0 += __shfl_xor_sync(0xffffffffu, ps0, 1);
        ps0 += __shfl_xor_sync(0xffffffffu, ps0, 2);
        ps1 += __shfl_xor_sync(0xffffffffu, ps1, 1);
        ps1 += __shfl_xor_sync(0xffffffffu, ps1, 2);
        l0 = l0 * cor0 + ps0;
        l1 = l1 * cor1 + ps1;
        #pragma unroll
        for (int nt = 0; nt < 4; nt++) {
            o[nt][0] *= cor0; o[nt][1] *= cor0;
            o[nt][2] *= cor1; o[nt][3] *= cor1;
        }
        __syncwarp();

        #pragma unroll
        for (int ks = 0; ks < 4; ks++) {
            unsigned a0, a1, a2, a3;
            LDSM4(a0, a1, a2, a3, pBase + ks * 32);
            #pragma unroll
            for (int dg = 0; dg < 2; dg++) {
                unsigned v0, v1, v2, v3;
                LDSM4T(v0, v1, v2, v3, vBase + ks * (16 * 112) + dg * 32);
                MMA_F16(o[dg*2  ][0], o[dg*2  ][1], o[dg*2  ][2], o[dg*2  ][3],
                        a0, a1, a2, a3, v0, v1);
                MMA_F16(o[dg*2+1][0], o[dg*2+1][1], o[dg*2+1][2], o[dg*2+1][3],
                        a0, a1, a2, a3, v2, v3);
            }
        }
    }

    const float inv0 = 1.0f / l0, inv1 = 1.0f / l1;
    const int row0 = b * 1024 + qt * 128 + w * 16 + g;
    #pragma unroll
    for (int nt = 0; nt < 4; nt++) {
        const int col = nh * 32 + nt * 8 + 2 * tig;
        size_t i0 = (size_t)row0 * HDIM + col;
        size_t i1 = (size_t)(row0 + 8) * HDIM + col;
        *(__half2*)(out + i0) = __floats2half2_rn(o[nt][0] * inv0, o[nt][1] * inv0);
        *(__half2*)(out + i1) = __floats2half2_rn(o[nt][2] * inv1, o[nt][3] * inv1);
    }
}

// ---------------- head final ------------------------------------------------
__global__ void head_final_kernel(const float* __restrict__ t, const float* __restrict__ w,
                                  const float* __restrict__ b, float* __restrict__ out) {
    int row = blockIdx.x * 8 + (threadIdx.x >> 5);
    int lane = threadIdx.x & 31;
    float acc = 0.f;
    #pragma unroll
    for (int i = lane; i < 128; i += 32)
        acc += t[(size_t)row * 128 + i] * w[i];
    #pragma unroll
    for (int ofs = 16; ofs; ofs >>= 1)
        acc += __shfl_xor_sync(0xffffffffu, acc, ofs);
    if (lane == 0)
        out[row] = 1.0f / (1.0f + expf(-(acc + b[0])));
}

// ---------------- host orchestration ----------------------------------------
extern "C" void kernel_launch(void* const* d_in, const int* in_sizes, int n_in,
                              void* d_out, int out_size) {
    const float* x        = (const float*)d_in[0];
    const int*   erow     = (const int*)  d_in[1];
    const int*   ecol     = (const int*)  d_in[2];
    const float* eval     = (const float*)d_in[3];
    const float* pe       = (const float*)d_in[4];
    const float* W_in     = (const float*)d_in[5];
    const float* b_in     = (const float*)d_in[6];
    const float* W_pe     = (const float*)d_in[7];
    const float* b_pe     = (const float*)d_in[8];
    const float* gcn_W    = (const float*)d_in[9];
    const float* ain_W    = (const float*)d_in[10];
    const float* ain_b    = (const float*)d_in[11];
    const float* aout_W   = (const float*)d_in[12];
    const float* aout_b   = (const float*)d_in[13];
    const float* bn_g     = (const float*)d_in[14];
    const float* bn_b     = (const float*)d_in[15];
    const float* ffn_W1   = (const float*)d_in[16];
    const float* ffn_b1   = (const float*)d_in[17];
    const float* ffn_W2   = (const float*)d_in[18];
    const float* ffn_b2   = (const float*)d_in[19];
    const float* head_W1  = (const float*)d_in[20];
    const float* head_b1  = (const float*)d_in[21];
    const float* head_W2  = (const float*)d_in[22];
    const float* head_b2  = (const float*)d_in[23];

    float *h, *t1, *psum, *psq, *stat, *statid, *bcat;
    __half *w16, *xpe16, *wcat16, *h16, *t1h, *t2h;
    int *cnt, *slot;
    cudaGetSymbolAddress((void**)&h,      g_h);
    cudaGetSymbolAddress((void**)&t1,     g_t1);
    cudaGetSymbolAddress((void**)&psum,   g_psum);
    cudaGetSymbolAddress((void**)&psq,    g_psq);
    cudaGetSymbolAddress((void**)&stat,   g_stat);
    cudaGetSymbolAddress((void**)&statid, g_statid);
    cudaGetSymbolAddress((void**)&bcat,   g_bcat);
    cudaGetSymbolAddress((void**)&cnt,    g_cnt);
    cudaGetSymbolAddress((void**)&slot,   g_slot);
    cudaGetSymbolAddress((void**)&w16,    g_w16);
    cudaGetSymbolAddress((void**)&xpe16,  g_xpe16);
    cudaGetSymbolAddress((void**)&wcat16, g_wcat16);
    cudaGetSymbolAddress((void**)&h16,    g_h16);
    cudaGetSymbolAddress((void**)&t1h,    g_t1h);
    cudaGetSymbolAddress((void**)&t2h,    g_t2h);

    cudaFuncSetAttribute(attn_h_kernel,
                         cudaFuncAttributeMaxDynamicSharedMemorySize, ATTN_SMEM);
    cudaFuncSetAttribute(gemm_h_kernel<64, 0, 0, false, 1>,
                         cudaFuncAttributeMaxDynamicSharedMemorySize, GEMM_SMEM_64);
    cudaFuncSetAttribute(gemm_h_kernel<64, 0, 0, false, 2>,
                         cudaFuncAttributeMaxDynamicSharedMemorySize, GEMM_SMEM_64);
    cudaFuncSetAttribute(gemm_h_kernel<64, 0, 2, true, 0>,
                         cudaFuncAttributeMaxDynamicSharedMemorySize, GEMM_SMEM_64);
    cudaFuncSetAttribute(gemm_h_kernel<64, 1, 0, false, 0>,
                         cudaFuncAttributeMaxDynamicSharedMemorySize, GEMM_SMEM_64);
    cudaFuncSetAttribute(gemm_h_kernel<128, 0, 0, false, 2>,
                         cudaFuncAttributeMaxDynamicSharedMemorySize, GEMM_SMEM_128);
    cudaFuncSetAttribute(gemm_h_kernel<128, 1, 0, false, 2>,
                         cudaFuncAttributeMaxDynamicSharedMemorySize, GEMM_SMEM_128);

    // prep: padded concat inputs/weights + bias sum + identity stat
    {
        int total = BNODES * (KPAD / 4) + HDIM * (KPAD / 4) + 64 + 128;
        prep_kernel<<<(total + 255) / 256, 256>>>(x, pe, W_in, W_pe, b_in, b_pe,
                                                  xpe16, wcat16, bcat, statid);
    }
    // weight conversion
    {
        ConvSegs segs;
        const float* srcs[NSEG] = {gcn_W, ain_W, aout_W, ffn_W1, ffn_W2, head_W1};
        __half* dsts[NSEG] = {w16 + OFF_GCN, w16 + OFF_AIN, w16 + OFF_AOUT,
                              w16 + OFF_FFN1, w16 + OFF_FFN2, w16 + OFF_HW1};
        int cnts[NSEG] = {NLAYER * HDIM * HDIM, NLAYER * 768 * HDIM,
                          NLAYER * HDIM * HDIM, NLAYER * 1024 * HDIM,
                          NLAYER * HDIM * 1024, 128 * HDIM};
        int cum = 0;
        for (int i = 0; i < NSEG; i++) {
            segs.src[i] = srcs[i];
            segs.dst[i] = dsts[i];
            segs.cum4[i] = cum;
            cum += cnts[i] / 4;
        }
        segs.cum4[NSEG] = cum;
        f2h_multi_kernel<<<(cum + 255) / 256, 256>>>(segs, cum);
    }

    // CSR build
    cudaMemsetAsync(cnt, 0, BNODES * sizeof(int));
    count_fill_kernel<<<NEDGE / 256, 256>>>(erow, cnt, slot);

    const dim3 g256 (2, BNODES / 64);
    const dim3 g768 (6, BNODES / 128);
    const dim3 g1024(8, BNODES / 128);
    const dim3 g128 (1, BNODES / 64);

    // merged input projection (K padded to 192, all slabs full cp.async)
    gemm_h_kernel<64, 0, 0, false, 1><<<g256, 256, GEMM_SMEM_64>>>(
        xpe16, wcat16, bcat, h, h16, nullptr, KPAD, HDIM);

    for (int l = 0; l < NLAYER; l++) {
        const float* statPrev = (l == 0) ? statid : stat;
        // ---- local GCN ----
        gemm_h_kernel<64, 0, 0, false, 2><<<g256, 256, GEMM_SMEM_64>>>(
            h16, w16 + OFF_GCN + (size_t)l * HDIM * HDIM, nullptr,
            nullptr, t1h, nullptr, HDIM, HDIM);
        gcn_gather_kernel<<<BNODES, 128>>>(t1h, cnt, slot, ecol, eval, t2h);
        bnpre_kernel<<<256, 256>>>(h, t2h, psum, psq, statPrev);
        bnstat_kernel<<<2, 128>>>(psum, psq, bn_g + l * 3 * HDIM,
                                  bn_b + l * 3 * HDIM, stat, 256);
        bnapply_kernel<<<256, 256>>>(h, h16, stat);
        // ---- global attention ----
        gemm_h_kernel<128, 0, 0, false, 2><<<g768, 256, GEMM_SMEM_128>>>(
            h16, w16 + OFF_AIN + (size_t)l * 768 * HDIM, ain_b + l * 768,
            nullptr, t1h, nullptr, HDIM, 768);
        attn_h_kernel<<<dim3(8, 8, 8), 256, ATTN_SMEM>>>(t1h, t2h);
        gemm_h_kernel<64, 0, 2, true, 0><<<g256, 256, GEMM_SMEM_64>>>(
            t2h, w16 + OFF_AOUT + (size_t)l * HDIM * HDIM, aout_b + l * HDIM,
            h, nullptr, stat, HDIM, HDIM);
        bnstat_kernel<<<2, 128>>>(psum, psq, bn_g + l * 3 * HDIM + HDIM,
                                  bn_b + l * 3 * HDIM + HDIM, stat, 128);
        bnapply_kernel<<<256, 256>>>(h, h16, stat);
        // ---- FFN ----
        gemm_h_kernel<128, 1, 0, false, 2><<<g1024, 256, GEMM_SMEM_128>>>(
            h16, w16 + OFF_FFN1 + (size_t)l * 1024 * HDIM, ffn_b1 + l * 1024,
            nullptr, t1h, nullptr, HDIM, 1024);
        gemm_h_kernel<64, 0, 2, true, 0><<<g256, 256, GEMM_SMEM_64>>>(
            t1h, w16 + OFF_FFN2 + (size_t)l * HDIM * 1024, ffn_b2 + l * HDIM,
            h, nullptr, stat, 1024, HDIM);
        bnstat_kernel<<<2, 128>>>(psum, psq, bn_g + l * 3 * HDIM + 2 * HDIM,
                                  bn_b + l * 3 * HDIM + 2 * HDIM, stat, 128);
        bnapply_kernel<<<256, 256>>>(h, h16, stat);
    }

    // ---- head ----
    gemm_h_kernel<64, 1, 0, false, 0><<<g128, 256, GEMM_SMEM_64>>>(
        h16, w16 + OFF_HW1, head_b1, t1, nullptr, nullptr, HDIM, 128);
    head_final_kernel<<<BNODES / 8, 256>>>(t1, head_W2, head_b2, (float*)d_out);
}

// round 16
// speedup vs baseline: 1.0250x; 1.0249x over previous
#include <cuda_runtime.h>
#include <cuda_fp16.h>
#include <math.h>

#define BNODES 8192
#define HDIM   256
#define NEDGE  131072
#define NLAYER 4
#define SLOTCAP 128

// fp32 scratch
__device__ float g_h [BNODES * HDIM];
__device__ float g_t1[BNODES * HDIM];
__device__ int   g_cnt[BNODES];
__device__ int   g_slot[BNODES * SLOTCAP];
__device__ float g_psum[256 * HDIM];
__device__ float g_psq [256 * HDIM];
__device__ float g_stat[2 * HDIM];     // A = istd*gamma, C = beta - mu*A
// fp16 scratch
__device__ __half g_w16[3475456];
__device__ __half g_x16[BNODES * 128];
__device__ __half g_pe16[BNODES * 8];
__device__ __half g_h16[BNODES * HDIM];
__device__ __half g_t1h[BNODES * 1024];
__device__ __half g_t2h[BNODES * HDIM];

#define OFF_WIN  0
#define OFF_WPE  32768
#define OFF_GCN  34816
#define OFF_AIN  296960
#define OFF_AOUT 1083392
#define OFF_FFN1 1345536
#define OFF_FFN2 2394112
#define OFF_HW1  3442688

__device__ __forceinline__ float gelu_f(float x) {
    return 0.5f * x * (1.0f + erff(x * 0.70710678118654752f));
}

__device__ __forceinline__ void cp_async16(void* smem_dst, const void* gmem_src) {
    unsigned s = (unsigned)__cvta_generic_to_shared(smem_dst);
    asm volatile("cp.async.cg.shared.global [%0], [%1], 16;\n" :: "r"(s), "l"(gmem_src));
}
#define CP_COMMIT() asm volatile("cp.async.commit_group;\n" ::: "memory")
#define CP_WAIT1()  asm volatile("cp.async.wait_group 1;\n" ::: "memory")
#define CP_WAIT0()  asm volatile("cp.async.wait_group 0;\n" ::: "memory")

#define MMA_F16(c0,c1,c2,c3, a0,a1,a2,a3, b0,b1)                           \
    asm volatile(                                                          \
        "mma.sync.aligned.m16n8k16.row.col.f32.f16.f16.f32 "               \
        "{%0,%1,%2,%3}, {%4,%5,%6,%7}, {%8,%9}, {%0,%1,%2,%3};\n"          \
        : "+f"(c0), "+f"(c1), "+f"(c2), "+f"(c3)                            \
        : "r"(a0), "r"(a1), "r"(a2), "r"(a3), "r"(b0), "r"(b1))

#define LDSM4(r0,r1,r2,r3, addr)                                            \
    asm volatile("ldmatrix.sync.aligned.m8n8.x4.shared.b16 {%0,%1,%2,%3}, [%4];" \
        : "=r"(r0), "=r"(r1), "=r"(r2), "=r"(r3) : "r"(addr))

#define LDSM4T(r0,r1,r2,r3, addr)                                           \
    asm volatile("ldmatrix.sync.aligned.m8n8.x4.trans.shared.b16 {%0,%1,%2,%3}, [%4];" \
        : "=r"(r0), "=r"(r1), "=r"(r2), "=r"(r3) : "r"(addr))

// ---------------- batched fp32 -> fp16 convert ------------------------------
#define NSEG 10
struct ConvSegs {
    const float* src[NSEG];
    __half*      dst[NSEG];
    int          cum4[NSEG + 1];
};

__global__ void f2h_multi_kernel(ConvSegs segs, int total4) {
    int i = blockIdx.x * 256 + threadIdx.x;
    if (i >= total4) return;
    int s = 0;
    #pragma unroll
    for (int k = 0; k < NSEG - 1; k++)
        if (i >= segs.cum4[k + 1]) s = k + 1;
    int j = i - segs.cum4[s];
    float4 v = ((const float4*)segs.src[s])[j];
    __half2* d = (__half2*)segs.dst[s];
    d[2 * j]     = __floats2half2_rn(v.x, v.y);
    d[2 * j + 1] = __floats2half2_rn(v.z, v.w);
}

// ---------------- fp16 GEMM (3-stage cp.async + ldmatrix, BK=64) -----------
template<int TM>
__device__ __forceinline__ void load_tile_h(
    const __half* __restrict__ A, const __half* __restrict__ W,
    __half (*As)[72], __half (*Bs)[72],
    int bm, int bn, int K, int k0, int tid) {
    #pragma unroll
    for (int i = 0; i < TM / 32; i++) {
        int idx = tid + i * 256;
        int r = idx >> 3, qd = idx & 7;
        const __half* src = A + (size_t)(bm + r) * K + k0 + qd * 8;
        __half* dst = &As[r][qd * 8];
        if (k0 + qd * 8 + 8 <= K) {
            cp_async16(dst, src);
        } else {
            #pragma unroll
            for (int j = 0; j < 8; j++)
                dst[j] = (k0 + qd * 8 + j < K) ? src[j] : __float2half(0.f);
        }
    }
    #pragma unroll
    for (int i = 0; i < 4; i++) {
        int idx = tid + i * 256;
        int r = idx >> 3, qd = idx & 7;
        const __half* src = W + (size_t)(bn + r) * K + k0 + qd * 8;
        __half* dst = &Bs[r][qd * 8];
        if (k0 + qd * 8 + 8 <= K) {
            cp_async16(dst, src);
        } else {
            #pragma unroll
            for (int j = 0; j < 8; j++)
                dst[j] = (k0 + qd * 8 + j < K) ? src[j] : __float2half(0.f);
        }
    }
    CP_COMMIT();
}

template<int TM, int ACT, int RES, bool STATS, int OM>
__global__ __launch_bounds__(256, 2)
void gemm_h_kernel(const __half* __restrict__ A, const __half* __restrict__ W,
                   const float* __restrict__ bias, float* __restrict__ C,
                   __half* __restrict__ C16, const float* __restrict__ stat,
                   int K, int N) {
    constexpr int MT = TM / 32;
    constexpr int RED_OFF = 3 * TM * 72 + 3 * 128 * 72;
    extern __shared__ __half hsm[];
    __half (*As)[72] = (__half(*)[72])hsm;
    __half (*Bs)[72] = (__half(*)[72])(hsm + 3 * TM * 72);

    const int bm = blockIdx.y * TM, bn = blockIdx.x * 128;
    const int tid  = threadIdx.x;
    const int lane = tid & 31;
    const int wid  = tid >> 5;
    const int wm   = wid >> 2;
    const int wn   = wid & 3;
    const int g    = lane >> 2;
    const int tig  = lane & 3;

    const unsigned aBase0 = (unsigned)__cvta_generic_to_shared(&As[0][0]);
    const unsigned bBase0 = aBase0 + 3 * TM * 72 * 2;
    const unsigned aLane = (unsigned)(wm * (TM / 2) + (lane & 15)) * 144
                         + ((lane >> 4) << 4);
    const unsigned bLane = (unsigned)(wn * 32 + ((lane >> 4) << 3) + (lane & 7)) * 144
                         + (((lane >> 3) & 1) << 4);

    float acc[MT][4][4] = {};

    const int KT = (K + 63) >> 6;
    load_tile_h<TM>(A, W, As, Bs, bm, bn, K, 0, tid);
    if (KT > 1)
        load_tile_h<TM>(A, W, As + TM, Bs + 128, bm, bn, K, 64, tid);

    for (int it = 0; it < KT; it++) {
        if (it + 1 < KT) CP_WAIT1(); else CP_WAIT0();
        __syncthreads();
        if (it + 2 < KT) {
            const int nb = (it + 2) % 3;
            load_tile_h<TM>(A, W, As + nb * TM, Bs + nb * 128,
                            bm, bn, K, (it + 2) * 64, tid);
        }

        const unsigned aB = aBase0 + (unsigned)((it % 3) * TM) * 144 + aLane;
        const unsigned bB = bBase0 + (unsigned)((it % 3) * 128) * 144 + bLane;

        #pragma unroll
        for (int ks = 0; ks < 4; ks++) {
            unsigned a[MT][4], b[4][2];
            #pragma unroll
            for (int mt = 0; mt < MT; mt++)
                LDSM4(a[mt][0], a[mt][1], a[mt][2], a[mt][3],
                      aB + mt * (16 * 144) + ks * 32);
            LDSM4(b[0][0], b[0][1], b[1][0], b[1][1], bB + ks * 32);
            LDSM4(b[2][0], b[2][1], b[3][0], b[3][1], bB + 16 * 144 + ks * 32);
            #pragma unroll
            for (int mt = 0; mt < MT; mt++)
                #pragma unroll
                for (int nt = 0; nt < 4; nt++)
                    MMA_F16(acc[mt][nt][0], acc[mt][nt][1],
                            acc[mt][nt][2], acc[mt][nt][3],
                            a[mt][0], a[mt][1], a[mt][2], a[mt][3],
                            b[nt][0], b[nt][1]);
        }
        __syncthreads();
    }

    float cs[4][2], cq[4][2];
    if (STATS) {
        #pragma unroll
        for (int nt = 0; nt < 4; nt++)
            cs[nt][0] = cs[nt][1] = cq[nt][0] = cq[nt][1] = 0.f;
    }

    #pragma unroll
    for (int mt = 0; mt < MT; mt++) {
        const int row = bm + wm * (TM / 2) + mt * 16 + g;
        #pragma unroll
        for (int nt = 0; nt < 4; nt++) {
            const int col = bn + wn * 32 + nt * 8 + 2 * tig;
            float b0 = 0.f, b1 = 0.f;
            if (bias) { b0 = bias[col]; b1 = bias[col + 1]; }
            float A0, A1, C0, C1;
            if (RES == 2) {
                A0 = stat[col]; A1 = stat[col + 1];
                C0 = stat[HDIM + col]; C1 = stat[HDIM + col + 1];
            }
            #pragma unroll
            for (int half_ = 0; half_ < 2; half_++) {
                const int r = row + half_ * 8;
                size_t idx = (size_t)r * N + col;
                float c0 = acc[mt][nt][half_ * 2 + 0] + b0;
                float c1 = acc[mt][nt][half_ * 2 + 1] + b1;
                if (RES == 1) { c0 += C[idx]; c1 += C[idx + 1]; }
                if (RES == 2) {
                    c0 += C[idx] * A0 + C0;
                    c1 += C[idx + 1] * A1 + C1;
                }
                if (ACT == 1) { c0 = gelu_f(c0); c1 = gelu_f(c1); }
                if (OM != 2) { C[idx] = c0; C[idx + 1] = c1; }
                if (OM >= 1)
                    *(__half2*)(C16 + idx) = __floats2half2_rn(c0, c1);
                if (STATS) {
                    cs[nt][0] += c0; cq[nt][0] += c0 * c0;
                    cs[nt][1] += c1; cq[nt][1] += c1 * c1;
                }
            }
        }
    }

    if (STATS) {
        float* sred = (float*)(hsm + RED_OFF);
        #pragma unroll
        for (int nt = 0; nt < 4; nt++)
            #pragma unroll
            for (int j = 0; j < 2; j++) {
                #pragma unroll
                for (int m = 4; m <= 16; m <<= 1) {
                    cs[nt][j] += __shfl_xor_sync(0xffffffffu, cs[nt][j], m);
                    cq[nt][j] += __shfl_xor_sync(0xffffffffu, cq[nt][j], m);
                }
            }
        if (g == 0) {
            #pragma unroll
            for (int nt = 0; nt < 4; nt++)
                #pragma unroll
                for (int j = 0; j < 2; j++) {
                    int c = wn * 32 + nt * 8 + 2 * tig + j;
                    sred[wm * 128 + c]       = cs[nt][j];
                    sred[256 + wm * 128 + c] = cq[nt][j];
                }
        }
        __syncthreads();
        if (tid < 128) {
            int c = tid;
            g_psum[blockIdx.y * HDIM + bn + c] = sred[c] + sred[128 + c];
            g_psq [blockIdx.y * HDIM + bn + c] = sred[256 + c] + sred[384 + c];
        }
    }
}

#define GEMM_SMEM_64  ((3 * 64 * 72 + 3 * 128 * 72) * 2 + 512 * 4)
#define GEMM_SMEM_128 ((3 * 128 * 72 + 3 * 128 * 72) * 2)

// ---------------- CSR build: fused count+fill -------------------------------
__global__ void count_fill_kernel(const int* __restrict__ row,
                                  int* __restrict__ cnt,
                                  int* __restrict__ slot) {
    int e = blockIdx.x * 256 + threadIdx.x;
    if (e < NEDGE) {
        int r = row[e];
        int p = atomicAdd(&cnt[r], 1);
        if (p < SLOTCAP) slot[r * SLOTCAP + p] = e;
    }
}

// ---------------- GCN gather -------------------------------------------------
__global__ void gcn_gather_kernel(const __half* __restrict__ t1h,
                                  const int* __restrict__ cnt,
                                  const int* __restrict__ slot,
                                  const int* __restrict__ ecol,
                                  const float* __restrict__ eval,
                                  __half* __restrict__ agg) {
    const int node = blockIdx.x;
    const int f2 = threadIdx.x;
    __shared__ int   scol[64];
    __shared__ float sval[64];
    const int n_e = min(cnt[node], SLOTCAP);
    float a0 = 0.f, a1 = 0.f;
    const __half2* t1h2 = (const __half2*)t1h;
    for (int base = 0; base < n_e; base += 64) {
        int n = min(64, n_e - base);
        if (f2 < n) {
            int e = slot[node * SLOTCAP + base + f2];
            scol[f2] = ecol[e];
            sval[f2] = eval[e];
        }
        __syncthreads();
        for (int j = 0; j < n; j++) {
            float2 v = __half22float2(t1h2[(size_t)scol[j] * 128 + f2]);
            a0 += sval[j] * v.x;
            a1 += sval[j] * v.y;
        }
        __syncthreads();
    }
    ((__half2*)agg)[(size_t)node * 128 + f2] = __floats2half2_rn(a0, a1);
}

// ---------------- BatchNorm -------------------------------------------------
template<bool FIRST>
__global__ void bnpre_kernel(float* __restrict__ h, const __half* __restrict__ add,
                             float* __restrict__ psum, float* __restrict__ psq,
                             const float* __restrict__ statPrev) {
    const int f = threadIdx.x;
    const int blk = blockIdx.x;
    float A = 1.f, C = 0.f;
    if (!FIRST) { A = statPrev[f]; C = statPrev[HDIM + f]; }
    float s = 0.f, sq = 0.f;
    size_t base = (size_t)blk * 32 * HDIM + f;
    #pragma unroll 4
    for (int r = 0; r < 32; r++) {
        size_t idx = base + (size_t)r * HDIM;
        float v = h[idx] * A + C + gelu_f(__half2float(add[idx]));
        h[idx] = v;
        s += v;
        sq += v * v;
    }
    psum[blk * HDIM + f] = s;
    psq [blk * HDIM + f] = sq;
}

__global__ void bnstat_kernel(const float* __restrict__ psum,
                              const float* __restrict__ psq,
                              const float* __restrict__ g,
                              const float* __restrict__ b,
                              float* __restrict__ stat, int npart) {
    const int f = blockIdx.x * 128 + threadIdx.x;
    float s = 0.f, sq = 0.f;
    for (int p = 0; p < npart; p++) { s += psum[p * HDIM + f]; sq += psq[p * HDIM + f]; }
    const float mu = s * (1.0f / BNODES);
    const float istd = rsqrtf(sq * (1.0f / BNODES) - mu * mu + 1e-5f);
    const float A = istd * g[f];
    stat[f]        = A;
    stat[HDIM + f] = b[f] - mu * A;
}

__global__ void bnapply_kernel(const float* __restrict__ h, __half* __restrict__ h16,
                               const float* __restrict__ stat) {
    const int cq = threadIdx.x & 63;
    const int ro = threadIdx.x >> 6;
    const float4 Av = *(const float4*)(stat + 4 * cq);
    const float4 Cv = *(const float4*)(stat + HDIM + 4 * cq);
    const float4* h4 = (const float4*)h;
    __half2* o2 = (__half2*)h16;
    const int row0 = blockIdx.x * 32 + ro * 8;
    #pragma unroll
    for (int i = 0; i < 8; i++) {
        size_t idx = (size_t)(row0 + i) * 64 + cq;
        float4 v = h4[idx];
        o2[2 * idx]     = __floats2half2_rn(v.x * Av.x + Cv.x, v.y * Av.y + Cv.y);
        o2[2 * idx + 1] = __floats2half2_rn(v.z * Av.z + Cv.z, v.w * Av.w + Cv.w);
    }
}

// ---------------- fp16 flash attention (3-buffer KV ring) -------------------
#define ATTN_SMEM ((3 * 64 * 56 + 3 * 64 * 56 + 128 * 72) * 2)

__global__ __launch_bounds__(256)
void attn_h_kernel(const __half* __restrict__ qkv, __half* __restrict__ out) {
    extern __shared__ __half hsm[];
    __half (*Kh)[64][56] = (__half(*)[64][56])hsm;
    __half (*Vh)[64][56] = (__half(*)[64][56])(hsm + 3 * 64 * 56);
    __half (*Sh)[72]     = (__half(*)[72])(hsm + 6 * 64 * 56);
    __half* Qs = (__half*)Sh;

    const int qt = blockIdx.x, nh = blockIdx.y, b = blockIdx.z;
    const int tid  = threadIdx.x;
    const int lane = tid & 31;
    const int w    = tid >> 5;
    const int g    = lane >> 2;
    const int tig  = lane & 3;
    const float scale = 0.17677669529663687f;
    const float L2E = 1.4426950408889634f;

    const size_t rowb = (size_t)(b * 1024) * 768 + nh * 32;

    {
        size_t qoff = rowb + (size_t)(qt * 128) * 768;
        #pragma unroll
        for (int i = 0; i < 2; i++) {
            int idx = tid + i * 256;
            int r = idx >> 2, qd = idx & 3;
            cp_async16(Qs + r * 56 + qd * 8, qkv + qoff + (size_t)r * 768 + qd * 8);
        }
        CP_COMMIT();
    }
    {
        int r = tid >> 2, qd = tid & 3;
        cp_async16(&Kh[0][r][qd * 8], qkv + rowb + (size_t)r * 768 + 256 + qd * 8);
        cp_async16(&Vh[0][r][qd * 8], qkv + rowb + (size_t)r * 768 + 512 + qd * 8);
        CP_COMMIT();
    }
    CP_WAIT1();
    __syncthreads();

    unsigned q[2][4];
    {
        unsigned qA = (unsigned)__cvta_generic_to_shared(Qs)
                    + (unsigned)(w * 16 + (lane & 15)) * 112 + ((lane >> 4) << 4);
        LDSM4(q[0][0], q[0][1], q[0][2], q[0][3], qA);
        LDSM4(q[1][0], q[1][1], q[1][2], q[1][3], qA + 32);
    }
    __syncthreads();

    const unsigned kLane = (unsigned)(((lane >> 4) << 3) + (lane & 7)) * 112
                         + (((lane >> 3) & 1) << 4);
    const unsigned pLane = (unsigned)(w * 16 + (lane & 15)) * 144 + ((lane >> 4) << 4);
    const unsigned vLane = (unsigned)((((lane >> 3) & 1) << 3) + (lane & 7)) * 112
                         + ((lane >> 4) << 4);
    const unsigned pBase = (unsigned)__cvta_generic_to_shared(&Sh[0][0]) + pLane;
    const int r0 = w * 16 + g;

    float m0 = -1e30f, m1 = -1e30f, l0 = 0.f, l1 = 0.f;
    float o[4][4] = {};

    for (int kt = 0; kt < 16; kt++) {
        if (kt + 1 < 16) {
            size_t koff = rowb + (size_t)((kt + 1) * 64) * 768;
            int st = (kt + 1) % 3;
            int r = tid >> 2, qd = tid & 3;
            cp_async16(&Kh[st][r][qd * 8], qkv + koff + (size_t)r * 768 + 256 + qd * 8);
            cp_async16(&Vh[st][r][qd * 8], qkv + koff + (size_t)r * 768 + 512 + qd * 8);
            CP_COMMIT();
            CP_WAIT1();
        } else {
            CP_WAIT0();
        }
        __syncthreads();

        const int cb = kt % 3;
        const unsigned kBase = (unsigned)__cvta_generic_to_shared(&Kh[cb][0][0]) + kLane;
        const unsigned vBase = (unsigned)__cvta_generic_to_shared(&Vh[cb][0][0]) + vLane;

        float s[8][4] = {};
        #pragma unroll
        for (int ks = 0; ks < 2; ks++) {
            #pragma unroll
            for (int grp = 0; grp < 4; grp++) {
                unsigned b0, b1, b2, b3;
                LDSM4(b0, b1, b2, b3, kBase + grp * (16 * 112) + ks * 32);
                MMA_F16(s[grp*2  ][0], s[grp*2  ][1], s[grp*2  ][2], s[grp*2  ][3],
                        q[ks][0], q[ks][1], q[ks][2], q[ks][3], b0, b1);
                MMA_F16(s[grp*2+1][0], s[grp*2+1][1], s[grp*2+1][2], s[grp*2+1][3],
                        q[ks][0], q[ks][1], q[ks][2], q[ks][3], b2, b3);
            }
        }

        float rmax0 = -1e30f, rmax1 = -1e30f;
        #pragma unroll
        for (int nt = 0; nt < 8; nt++) {
            s[nt][0] *= scale; s[nt][1] *= scale;
            s[nt][2] *= scale; s[nt][3] *= scale;
            rmax0 = fmaxf(rmax0, fmaxf(s[nt][0], s[nt][1]));
            rmax1 = fmaxf(rmax1, fmaxf(s[nt][2], s[nt][3]));
        }
        rmax0 = fmaxf(rmax0, __shfl_xor_sync(0xffffffffu, rmax0, 1));
        rmax0 = fmaxf(rmax0, __shfl_xor_sync(0xffffffffu, rmax0, 2));
        rmax1 = fmaxf(rmax1, __shfl_xor_sync(0xffffffffu, rmax1, 1));
        rmax1 = fmaxf(rmax1, __shfl_xor_sync(0xffffffffu, rmax1, 2));

        float mn0 = fmaxf(m0, rmax0), mn1 = fmaxf(m1, rmax1);
        float cor0 = __expf(m0 - mn0), cor1 = __expf(m1 - mn1);
        m0 = mn0; m1 = mn1;
        const float mL0 = mn0 * L2E, mL1 = mn1 * L2E;

        float ps0 = 0.f, ps1 = 0.f;
        #pragma unroll
        for (int nt = 0; nt < 8; nt++) {
            __half2 hp0 = h2exp2(__floats2half2_rn(fmaf(s[nt][0], L2E, -mL0),
                                                   fmaf(s[nt][1], L2E, -mL0)));
            __half2 hp1 = h2exp2(__floats2half2_rn(fmaf(s[nt][2], L2E, -mL1),
                                                   fmaf(s[nt][3], L2E, -mL1)));
            int c = nt * 8 + 2 * tig;
            *(__half2*)&Sh[r0    ][c] = hp0;
            *(__half2*)&Sh[r0 + 8][c] = hp1;
            float2 p0 = __half22float2(hp0);
            float2 p1 = __half22float2(hp1);
            ps0 += p0.x + p0.y;
            ps1 += p1.x + p1.y;
        }
        ps0 += __shfl_xor_sync(0xffffffffu, ps0, 1);
        ps0 += __shfl_xor_sync(0xffffffffu, ps0, 2);
        ps1 += __shfl_xor_sync(0xffffffffu, ps1, 1);
        ps1 += __shfl_xor_sync(0xffffffffu, ps1, 2);
        l0 = l0 * cor0 + ps0;
        l1 = l1 * cor1 + ps1;
        #pragma unroll
        for (int nt = 0; nt < 4; nt++) {
            o[nt][0] *= cor0; o[nt][1] *= cor0;
            o[nt][2] *= cor1; o[nt][3] *= cor1;
        }
        __syncwarp();

        #pragma unroll
        for (int ks = 0; ks < 4; ks++) {
            unsigned a0, a1, a2, a3;
            LDSM4(a0, a1, a2, a3, pBase + ks * 32);
            #pragma unroll
            for (int dg = 0; dg < 2; dg++) {
                unsigned v0, v1, v2, v3;
                LDSM4T(v0, v1, v2, v3, vBase + ks * (16 * 112) + dg * 32);
                MMA_F16(o[dg*2  ][0], o[dg*2  ][1], o[dg*2  ][2], o[dg*2  ][3],
                        a0, a1, a2, a3, v0, v1);
                MMA_F16(o[dg*2+1][0], o[dg*2+1][1], o[dg*2+1][2], o[dg*2+1][3],
                        a0, a1, a2, a3, v2, v3);
            }
        }
    }

    const float inv0 = 1.0f / l0, inv1 = 1.0f / l1;
    const int row0 = b * 1024 + qt * 128 + w * 16 + g;
    #pragma unroll
    for (int nt = 0; nt < 4; nt++) {
        const int col = nh * 32 + nt * 8 + 2 * tig;
        size_t i0 = (size_t)row0 * HDIM + col;
        size_t i1 = (size_t)(row0 + 8) * HDIM + col;
        *(__half2*)(out + i0) = __floats2half2_rn(o[nt][0] * inv0, o[nt][1] * inv0);
        *(__half2*)(out + i1) = __floats2half2_rn(o[nt][2] * inv1, o[nt][3] * inv1);
    }
}

// ---------------- head final ------------------------------------------------
__global__ void head_final_kernel(const float* __restrict__ t, const float* __restrict__ w,
                                  const float* __restrict__ b, float* __restrict__ out) {
    int row = blockIdx.x * 8 + (threadIdx.x >> 5);
    int lane = threadIdx.x & 31;
    float acc = 0.f;
    #pragma unroll
    for (int i = lane; i < 128; i += 32)
        acc += t[(size_t)row * 128 + i] * w[i];
    #pragma unroll
    for (int ofs = 16; ofs; ofs >>= 1)
        acc += __shfl_xor_sync(0xffffffffu, acc, ofs);
    if (lane == 0)
        out[row] = 1.0f / (1.0f + expf(-(acc + b[0])));
}

// ---------------- host orchestration ----------------------------------------
extern "C" void kernel_launch(void* const* d_in, const int* in_sizes, int n_in,
                              void* d_out, int out_size) {
    const float* x        = (const float*)d_in[0];
    const int*   erow     = (const int*)  d_in[1];
    const int*   ecol     = (const int*)  d_in[2];
    const float* eval     = (const float*)d_in[3];
    const float* pe       = (const float*)d_in[4];
    const float* W_in     = (const float*)d_in[5];
    const float* b_in     = (const float*)d_in[6];
    const float* W_pe     = (const float*)d_in[7];
    const float* b_pe     = (const float*)d_in[8];
    const float* gcn_W    = (const float*)d_in[9];
    const float* ain_W    = (const float*)d_in[10];
    const float* ain_b    = (const float*)d_in[11];
    const float* aout_W   = (const float*)d_in[12];
    const float* aout_b   = (const float*)d_in[13];
    const float* bn_g     = (const float*)d_in[14];
    const float* bn_b     = (const float*)d_in[15];
    const float* ffn_W1   = (const float*)d_in[16];
    const float* ffn_b1   = (const float*)d_in[17];
    const float* ffn_W2   = (const float*)d_in[18];
    const float* ffn_b2   = (const float*)d_in[19];
    const float* head_W1  = (const float*)d_in[20];
    const float* head_b1  = (const float*)d_in[21];
    const float* head_W2  = (const float*)d_in[22];
    const float* head_b2  = (const float*)d_in[23];

    float *h, *t1, *psum, *psq, *stat;
    __half *w16, *x16, *pe16, *h16, *t1h, *t2h;
    int *cnt, *slot;
    cudaGetSymbolAddress((void**)&h,      g_h);
    cudaGetSymbolAddress((void**)&t1,     g_t1);
    cudaGetSymbolAddress((void**)&psum,   g_psum);
    cudaGetSymbolAddress((void**)&psq,    g_psq);
    cudaGetSymbolAddress((void**)&stat,   g_stat);
    cudaGetSymbolAddress((void**)&cnt,    g_cnt);
    cudaGetSymbolAddress((void**)&slot,   g_slot);
    cudaGetSymbolAddress((void**)&w16,    g_w16);
    cudaGetSymbolAddress((void**)&x16,    g_x16);
    cudaGetSymbolAddress((void**)&pe16,   g_pe16);
    cudaGetSymbolAddress((void**)&h16,    g_h16);
    cudaGetSymbolAddress((void**)&t1h,    g_t1h);
    cudaGetSymbolAddress((void**)&t2h,    g_t2h);

    cudaFuncSetAttribute(attn_h_kernel,
                         cudaFuncAttributeMaxDynamicSharedMemorySize, ATTN_SMEM);
    cudaFuncSetAttribute(gemm_h_kernel<64, 0, 0, false, 0>,
                         cudaFuncAttributeMaxDynamicSharedMemorySize, GEMM_SMEM_64);
    cudaFuncSetAttribute(gemm_h_kernel<64, 0, 1, false, 1>,
                         cudaFuncAttributeMaxDynamicSharedMemorySize, GEMM_SMEM_64);
    cudaFuncSetAttribute(gemm_h_kernel<64, 0, 0, false, 2>,
                         cudaFuncAttributeMaxDynamicSharedMemorySize, GEMM_SMEM_64);
    cudaFuncSetAttribute(gemm_h_kernel<64, 0, 2, true, 0>,
                         cudaFuncAttributeMaxDynamicSharedMemorySize, GEMM_SMEM_64);
    cudaFuncSetAttribute(gemm_h_kernel<64, 1, 0, false, 0>,
                         cudaFuncAttributeMaxDynamicSharedMemorySize, GEMM_SMEM_64);
    cudaFuncSetAttribute(gemm_h_kernel<128, 0, 0, false, 2>,
                         cudaFuncAttributeMaxDynamicSharedMemorySize, GEMM_SMEM_128);
    cudaFuncSetAttribute(gemm_h_kernel<128, 1, 0, false, 2>,
                         cudaFuncAttributeMaxDynamicSharedMemorySize, GEMM_SMEM_128);

    // batched fp16 conversion (inputs + all weights, single launch)
    {
        ConvSegs segs;
        const float* srcs[NSEG] = {x, pe, W_in, W_pe, gcn_W, ain_W, aout_W,
                                   ffn_W1, ffn_W2, head_W1};
        __half* dsts[NSEG] = {x16, pe16, w16 + OFF_WIN, w16 + OFF_WPE,
                              w16 + OFF_GCN, w16 + OFF_AIN, w16 + OFF_AOUT,
                              w16 + OFF_FFN1, w16 + OFF_FFN2, w16 + OFF_HW1};
        int cnts[NSEG] = {BNODES * 128, BNODES * 8, HDIM * 128, HDIM * 8,
                          NLAYER * HDIM * HDIM, NLAYER * 768 * HDIM,
                          NLAYER * HDIM * HDIM, NLAYER * 1024 * HDIM,
                          NLAYER * HDIM * 1024, 128 * HDIM};
        int cum = 0;
        for (int i = 0; i < NSEG; i++) {
            segs.src[i] = srcs[i];
            segs.dst[i] = dsts[i];
            segs.cum4[i] = cum;
            cum += cnts[i] / 4;
        }
        segs.cum4[NSEG] = cum;
        f2h_multi_kernel<<<(cum + 255) / 256, 256>>>(segs, cum);
    }

    // CSR build: single fused count+fill
    cudaMemsetAsync(cnt, 0, BNODES * sizeof(int));
    count_fill_kernel<<<NEDGE / 256, 256>>>(erow, cnt, slot);

    const dim3 g256 (2, BNODES / 64);
    const dim3 g768 (6, BNODES / 128);
    const dim3 g1024(8, BNODES / 128);
    const dim3 g128 (1, BNODES / 64);

    // input projection: two GEMMs (proven fastest path)
    gemm_h_kernel<64, 0, 0, false, 0><<<g256, 256, GEMM_SMEM_64>>>(
        x16, w16 + OFF_WIN, b_in, h, nullptr, nullptr, 128, HDIM);
    gemm_h_kernel<64, 0, 1, false, 1><<<g256, 256, GEMM_SMEM_64>>>(
        pe16, w16 + OFF_WPE, b_pe, h, h16, nullptr, 8, HDIM);

    for (int l = 0; l < NLAYER; l++) {
        // ---- local GCN ----
        gemm_h_kernel<64, 0, 0, false, 2><<<g256, 256, GEMM_SMEM_64>>>(
            h16, w16 + OFF_GCN + (size_t)l * HDIM * HDIM, nullptr,
            nullptr, t1h, nullptr, HDIM, HDIM);
        gcn_gather_kernel<<<BNODES, 128>>>(t1h, cnt, slot, ecol, eval, t2h);
        if (l == 0) bnpre_kernel<true ><<<256, 256>>>(h, t2h, psum, psq, stat);
        else        bnpre_kernel<false><<<256, 256>>>(h, t2h, psum, psq, stat);
        bnstat_kernel<<<2, 128>>>(psum, psq, bn_g + l * 3 * HDIM,
                                  bn_b + l * 3 * HDIM, stat, 256);
        bnapply_kernel<<<256, 256>>>(h, h16, stat);
        // ---- global attention ----
        gemm_h_kernel<128, 0, 0, false, 2><<<g768, 256, GEMM_SMEM_128>>>(
            h16, w16 + OFF_AIN + (size_t)l * 768 * HDIM, ain_b + l * 768,
            nullptr, t1h, nullptr, HDIM, 768);
        attn_h_kernel<<<dim3(8, 8, 8), 256, ATTN_SMEM>>>(t1h, t2h);
        gemm_h_kernel<64, 0, 2, true, 0><<<g256, 256, GEMM_SMEM_64>>>(
            t2h, w16 + OFF_AOUT + (size_t)l * HDIM * HDIM, aout_b + l * HDIM,
            h, nullptr, stat, HDIM, HDIM);
        bnstat_kernel<<<2, 128>>>(psum, psq, bn_g + l * 3 * HDIM + HDIM,
                                  bn_b + l * 3 * HDIM + HDIM, stat, 128);
        bnapply_kernel<<<256, 256>>>(h, h16, stat);
        // ---- FFN ----
        gemm_h_kernel<128, 1, 0, false, 2><<<g1024, 256, GEMM_SMEM_128>>>(
            h16, w16 + OFF_FFN1 + (size_t)l * 1024 * HDIM, ffn_b1 + l * 1024,
            nullptr, t1h, nullptr, HDIM, 1024);
        gemm_h_kernel<64, 0, 2, true, 0><<<g256, 256, GEMM_SMEM_64>>>(
            t1h, w16 + OFF_FFN2 + (size_t)l * HDIM * 1024, ffn_b2 + l * HDIM,
            h, nullptr, stat, 1024, HDIM);
        bnstat_kernel<<<2, 128>>>(psum, psq, bn_g + l * 3 * HDIM + 2 * HDIM,
                                  bn_b + l * 3 * HDIM + 2 * HDIM, stat, 128);
        bnapply_kernel<<<256, 256>>>(h, h16, stat);
    }

    // ---- head ----
    gemm_h_kernel<64, 1, 0, false, 0><<<g128, 256, GEMM_SMEM_64>>>(
        h16, w16 + OFF_HW1, head_b1, t1, nullptr, nullptr, HDIM, 128);
    head_final_kernel<<<BNODES / 8, 256>>>(t1, head_W2, head_b2, (float*)d_out);
}

// round 17
// speedup vs baseline: 1.0391x; 1.0137x over previous
#include <cuda_runtime.h>
#include <cuda_fp16.h>
#include <math.h>

#define BNODES 8192
#define HDIM   256
#define NEDGE  131072
#define NLAYER 4
#define SLOTCAP 128

// fp32 scratch
__device__ float g_h [BNODES * HDIM];
__device__ float g_t1[BNODES * HDIM];
__device__ int   g_cnt[BNODES];
__device__ int   g_slot[BNODES * SLOTCAP];
__device__ float g_psum[256 * HDIM];
__device__ float g_psq [256 * HDIM];
__device__ float g_stat[2 * HDIM];     // A = istd*gamma, C = beta - mu*A
// fp16 scratch
__device__ __half g_w16[3475456];
__device__ __half g_x16[BNODES * 128];
__device__ __half g_pe16[BNODES * 8];
__device__ __half g_h16[BNODES * HDIM];
__device__ __half g_t1h[BNODES * 1024];
__device__ __half g_t2h[BNODES * HDIM];

#define OFF_WIN  0
#define OFF_WPE  32768
#define OFF_GCN  34816
#define OFF_AIN  296960
#define OFF_AOUT 1083392
#define OFF_FFN1 1345536
#define OFF_FFN2 2394112
#define OFF_HW1  3442688

__device__ __forceinline__ float gelu_f(float x) {
    return 0.5f * x * (1.0f + erff(x * 0.70710678118654752f));
}

__device__ __forceinline__ void cp_async16(void* smem_dst, const void* gmem_src) {
    unsigned s = (unsigned)__cvta_generic_to_shared(smem_dst);
    asm volatile("cp.async.cg.shared.global [%0], [%1], 16;\n" :: "r"(s), "l"(gmem_src));
}
#define CP_COMMIT() asm volatile("cp.async.commit_group;\n" ::: "memory")
#define CP_WAIT1()  asm volatile("cp.async.wait_group 1;\n" ::: "memory")
#define CP_WAIT0()  asm volatile("cp.async.wait_group 0;\n" ::: "memory")

#define MMA_F16(c0,c1,c2,c3, a0,a1,a2,a3, b0,b1)                           \
    asm volatile(                                                          \
        "mma.sync.aligned.m16n8k16.row.col.f32.f16.f16.f32 "               \
        "{%0,%1,%2,%3}, {%4,%5,%6,%7}, {%8,%9}, {%0,%1,%2,%3};\n"          \
        : "+f"(c0), "+f"(c1), "+f"(c2), "+f"(c3)                            \
        : "r"(a0), "r"(a1), "r"(a2), "r"(a3), "r"(b0), "r"(b1))

#define LDSM4(r0,r1,r2,r3, addr)                                            \
    asm volatile("ldmatrix.sync.aligned.m8n8.x4.shared.b16 {%0,%1,%2,%3}, [%4];" \
        : "=r"(r0), "=r"(r1), "=r"(r2), "=r"(r3) : "r"(addr))

#define LDSM4T(r0,r1,r2,r3, addr)                                           \
    asm volatile("ldmatrix.sync.aligned.m8n8.x4.trans.shared.b16 {%0,%1,%2,%3}, [%4];" \
        : "=r"(r0), "=r"(r1), "=r"(r2), "=r"(r3) : "r"(addr))

// ---------------- batched fp32 -> fp16 convert ------------------------------
#define NSEG 10
struct ConvSegs {
    const float* src[NSEG];
    __half*      dst[NSEG];
    int          cum4[NSEG + 1];
};

__global__ void f2h_multi_kernel(ConvSegs segs, int total4) {
    int i = blockIdx.x * 256 + threadIdx.x;
    if (i >= total4) return;
    int s = 0;
    #pragma unroll
    for (int k = 0; k < NSEG - 1; k++)
        if (i >= segs.cum4[k + 1]) s = k + 1;
    int j = i - segs.cum4[s];
    float4 v = ((const float4*)segs.src[s])[j];
    __half2* d = (__half2*)segs.dst[s];
    d[2 * j]     = __floats2half2_rn(v.x, v.y);
    d[2 * j + 1] = __floats2half2_rn(v.z, v.w);
}

// ---------------- fp16 GEMM (3-stage cp.async + ldmatrix, BK=64) -----------
// PEF: fuse rank-8 pe@W_pe^T (+b_pe) update into the epilogue.
template<int TM>
__device__ __forceinline__ void load_tile_h(
    const __half* __restrict__ A, const __half* __restrict__ W,
    __half (*As)[72], __half (*Bs)[72],
    int bm, int bn, int K, int k0, int tid) {
    #pragma unroll
    for (int i = 0; i < TM / 32; i++) {
        int idx = tid + i * 256;
        int r = idx >> 3, qd = idx & 7;
        const __half* src = A + (size_t)(bm + r) * K + k0 + qd * 8;
        __half* dst = &As[r][qd * 8];
        if (k0 + qd * 8 + 8 <= K) {
            cp_async16(dst, src);
        } else {
            #pragma unroll
            for (int j = 0; j < 8; j++)
                dst[j] = (k0 + qd * 8 + j < K) ? src[j] : __float2half(0.f);
        }
    }
    #pragma unroll
    for (int i = 0; i < 4; i++) {
        int idx = tid + i * 256;
        int r = idx >> 3, qd = idx & 7;
        const __half* src = W + (size_t)(bn + r) * K + k0 + qd * 8;
        __half* dst = &Bs[r][qd * 8];
        if (k0 + qd * 8 + 8 <= K) {
            cp_async16(dst, src);
        } else {
            #pragma unroll
            for (int j = 0; j < 8; j++)
                dst[j] = (k0 + qd * 8 + j < K) ? src[j] : __float2half(0.f);
        }
    }
    CP_COMMIT();
}

template<int TM, int ACT, int RES, bool STATS, int OM, bool PEF>
__global__ __launch_bounds__(256, 2)
void gemm_h_kernel(const __half* __restrict__ A, const __half* __restrict__ W,
                   const float* __restrict__ bias, float* __restrict__ C,
                   __half* __restrict__ C16, const float* __restrict__ stat,
                   const __half* __restrict__ pe, const __half* __restrict__ peW,
                   const float* __restrict__ peB, int K, int N) {
    constexpr int MT = TM / 32;
    constexpr int RED_OFF = 3 * TM * 72 + 3 * 128 * 72;   // halves
    extern __shared__ __half hsm[];
    __half (*As)[72] = (__half(*)[72])hsm;
    __half (*Bs)[72] = (__half(*)[72])(hsm + 3 * TM * 72);

    const int bm = blockIdx.y * TM, bn = blockIdx.x * 128;
    const int tid  = threadIdx.x;
    const int lane = tid & 31;
    const int wid  = tid >> 5;
    const int wm   = wid >> 2;
    const int wn   = wid & 3;
    const int g    = lane >> 2;
    const int tig  = lane & 3;

    const unsigned aBase0 = (unsigned)__cvta_generic_to_shared(&As[0][0]);
    const unsigned bBase0 = aBase0 + 3 * TM * 72 * 2;
    const unsigned aLane = (unsigned)(wm * (TM / 2) + (lane & 15)) * 144
                         + ((lane >> 4) << 4);
    const unsigned bLane = (unsigned)(wn * 32 + ((lane >> 4) << 3) + (lane & 7)) * 144
                         + (((lane >> 3) & 1) << 4);

    // PEF staging: W_pe block (128x8 fp32) + b_pe block (128) into smem.
    // Visibility is guaranteed by the first mainloop __syncthreads.
    float* wpe_s = (float*)(hsm + RED_OFF);    // 1024 floats
    float* bpe_s = wpe_s + 1024;               // 128 floats
    if (PEF && tid < 128) {
        const __half* src = peW + (size_t)(bn + tid) * 8;
        #pragma unroll
        for (int j = 0; j < 8; j++) wpe_s[tid * 8 + j] = __half2float(src[j]);
        bpe_s[tid] = peB[bn + tid];
    }

    float acc[MT][4][4] = {};

    const int KT = (K + 63) >> 6;
    load_tile_h<TM>(A, W, As, Bs, bm, bn, K, 0, tid);
    if (KT > 1)
        load_tile_h<TM>(A, W, As + TM, Bs + 128, bm, bn, K, 64, tid);

    for (int it = 0; it < KT; it++) {
        if (it + 1 < KT) CP_WAIT1(); else CP_WAIT0();
        __syncthreads();
        if (it + 2 < KT) {
            const int nb = (it + 2) % 3;
            load_tile_h<TM>(A, W, As + nb * TM, Bs + nb * 128,
                            bm, bn, K, (it + 2) * 64, tid);
        }

        const unsigned aB = aBase0 + (unsigned)((it % 3) * TM) * 144 + aLane;
        const unsigned bB = bBase0 + (unsigned)((it % 3) * 128) * 144 + bLane;

        #pragma unroll
        for (int ks = 0; ks < 4; ks++) {
            unsigned a[MT][4], b[4][2];
            #pragma unroll
            for (int mt = 0; mt < MT; mt++)
                LDSM4(a[mt][0], a[mt][1], a[mt][2], a[mt][3],
                      aB + mt * (16 * 144) + ks * 32);
            LDSM4(b[0][0], b[0][1], b[1][0], b[1][1], bB + ks * 32);
            LDSM4(b[2][0], b[2][1], b[3][0], b[3][1], bB + 16 * 144 + ks * 32);
            #pragma unroll
            for (int mt = 0; mt < MT; mt++)
                #pragma unroll
                for (int nt = 0; nt < 4; nt++)
                    MMA_F16(acc[mt][nt][0], acc[mt][nt][1],
                            acc[mt][nt][2], acc[mt][nt][3],
                            a[mt][0], a[mt][1], a[mt][2], a[mt][3],
                            b[nt][0], b[nt][1]);
        }
        __syncthreads();
    }

    float cs[4][2], cq[4][2];
    if (STATS) {
        #pragma unroll
        for (int nt = 0; nt < 4; nt++)
            cs[nt][0] = cs[nt][1] = cq[nt][0] = cq[nt][1] = 0.f;
    }

    #pragma unroll
    for (int mt = 0; mt < MT; mt++) {
        const int row = bm + wm * (TM / 2) + mt * 16 + g;
        float pef[2][8];
        if (PEF) {
            #pragma unroll
            for (int hh = 0; hh < 2; hh++) {
                uint4 v = *(const uint4*)(pe + (size_t)(row + hh * 8) * 8);
                const __half* hv = (const __half*)&v;
                #pragma unroll
                for (int j = 0; j < 8; j++) pef[hh][j] = __half2float(hv[j]);
            }
        }
        #pragma unroll
        for (int nt = 0; nt < 4; nt++) {
            const int col = bn + wn * 32 + nt * 8 + 2 * tig;
            const int cl  = wn * 32 + nt * 8 + 2 * tig;
            float b0 = 0.f, b1 = 0.f;
            if (bias) { b0 = bias[col]; b1 = bias[col + 1]; }
            float A0, A1, C0, C1;
            if (RES == 2) {
                A0 = stat[col]; A1 = stat[col + 1];
                C0 = stat[HDIM + col]; C1 = stat[HDIM + col + 1];
            }
            #pragma unroll
            for (int half_ = 0; half_ < 2; half_++) {
                const int r = row + half_ * 8;
                size_t idx = (size_t)r * N + col;
                float c0 = acc[mt][nt][half_ * 2 + 0] + b0;
                float c1 = acc[mt][nt][half_ * 2 + 1] + b1;
                if (RES == 1) { c0 += C[idx]; c1 += C[idx + 1]; }
                if (RES == 2) {
                    c0 += C[idx] * A0 + C0;
                    c1 += C[idx + 1] * A1 + C1;
                }
                if (PEF) {
                    float d0 = bpe_s[cl], d1 = bpe_s[cl + 1];
                    #pragma unroll
                    for (int j = 0; j < 8; j++) {
                        d0 = fmaf(pef[half_][j], wpe_s[cl * 8 + j], d0);
                        d1 = fmaf(pef[half_][j], wpe_s[(cl + 1) * 8 + j], d1);
                    }
                    c0 += d0; c1 += d1;
                }
                if (ACT == 1) { c0 = gelu_f(c0); c1 = gelu_f(c1); }
                if (OM != 2) { C[idx] = c0; C[idx + 1] = c1; }
                if (OM >= 1)
                    *(__half2*)(C16 + idx) = __floats2half2_rn(c0, c1);
                if (STATS) {
                    cs[nt][0] += c0; cq[nt][0] += c0 * c0;
                    cs[nt][1] += c1; cq[nt][1] += c1 * c1;
                }
            }
        }
    }

    if (STATS) {
        float* sred = (float*)(hsm + RED_OFF);
        #pragma unroll
        for (int nt = 0; nt < 4; nt++)
            #pragma unroll
            for (int j = 0; j < 2; j++) {
                #pragma unroll
                for (int m = 4; m <= 16; m <<= 1) {
                    cs[nt][j] += __shfl_xor_sync(0xffffffffu, cs[nt][j], m);
                    cq[nt][j] += __shfl_xor_sync(0xffffffffu, cq[nt][j], m);
                }
            }
        if (g == 0) {
            #pragma unroll
            for (int nt = 0; nt < 4; nt++)
                #pragma unroll
                for (int j = 0; j < 2; j++) {
                    int c = wn * 32 + nt * 8 + 2 * tig + j;
                    sred[wm * 128 + c]       = cs[nt][j];
                    sred[256 + wm * 128 + c] = cq[nt][j];
                }
        }
        __syncthreads();
        if (tid < 128) {
            int c = tid;
            g_psum[blockIdx.y * HDIM + bn + c] = sred[c] + sred[128 + c];
            g_psq [blockIdx.y * HDIM + bn + c] = sred[256 + c] + sred[384 + c];
        }
    }
}

#define GEMM_SMEM_64  ((3 * 64 * 72 + 3 * 128 * 72) * 2 + 1152 * 4)
#define GEMM_SMEM_128 ((3 * 128 * 72 + 3 * 128 * 72) * 2)

// ---------------- CSR build: fused count+fill -------------------------------
__global__ void count_fill_kernel(const int* __restrict__ row,
                                  int* __restrict__ cnt,
                                  int* __restrict__ slot) {
    int e = blockIdx.x * 256 + threadIdx.x;
    if (e < NEDGE) {
        int r = row[e];
        int p = atomicAdd(&cnt[r], 1);
        if (p < SLOTCAP) slot[r * SLOTCAP + p] = e;
    }
}

// ---------------- GCN gather -------------------------------------------------
__global__ void gcn_gather_kernel(const __half* __restrict__ t1h,
                                  const int* __restrict__ cnt,
                                  const int* __restrict__ slot,
                                  const int* __restrict__ ecol,
                                  const float* __restrict__ eval,
                                  __half* __restrict__ agg) {
    const int node = blockIdx.x;
    const int f2 = threadIdx.x;
    __shared__ int   scol[64];
    __shared__ float sval[64];
    const int n_e = min(cnt[node], SLOTCAP);
    float a0 = 0.f, a1 = 0.f;
    const __half2* t1h2 = (const __half2*)t1h;
    for (int base = 0; base < n_e; base += 64) {
        int n = min(64, n_e - base);
        if (f2 < n) {
            int e = slot[node * SLOTCAP + base + f2];
            scol[f2] = ecol[e];
            sval[f2] = eval[e];
        }
        __syncthreads();
        for (int j = 0; j < n; j++) {
            float2 v = __half22float2(t1h2[(size_t)scol[j] * 128 + f2]);
            a0 += sval[j] * v.x;
            a1 += sval[j] * v.y;
        }
        __syncthreads();
    }
    ((__half2*)agg)[(size_t)node * 128 + f2] = __floats2half2_rn(a0, a1);
}

// ---------------- BatchNorm -------------------------------------------------
template<bool FIRST>
__global__ void bnpre_kernel(float* __restrict__ h, const __half* __restrict__ add,
                             float* __restrict__ psum, float* __restrict__ psq,
                             const float* __restrict__ statPrev) {
    const int f = threadIdx.x;
    const int blk = blockIdx.x;
    float A = 1.f, C = 0.f;
    if (!FIRST) { A = statPrev[f]; C = statPrev[HDIM + f]; }
    float s = 0.f, sq = 0.f;
    size_t base = (size_t)blk * 32 * HDIM + f;
    #pragma unroll 4
    for (int r = 0; r < 32; r++) {
        size_t idx = base + (size_t)r * HDIM;
        float v = h[idx] * A + C + gelu_f(__half2float(add[idx]));
        h[idx] = v;
        s += v;
        sq += v * v;
    }
    psum[blk * HDIM + f] = s;
    psq [blk * HDIM + f] = sq;
}

__global__ void bnstat_kernel(const float* __restrict__ psum,
                              const float* __restrict__ psq,
                              const float* __restrict__ g,
                              const float* __restrict__ b,
                              float* __restrict__ stat, int npart) {
    const int f = blockIdx.x * 128 + threadIdx.x;
    float s = 0.f, sq = 0.f;
    for (int p = 0; p < npart; p++) { s += psum[p * HDIM + f]; sq += psq[p * HDIM + f]; }
    const float mu = s * (1.0f / BNODES);
    const float istd = rsqrtf(sq * (1.0f / BNODES) - mu * mu + 1e-5f);
    const float A = istd * g[f];
    stat[f]        = A;
    stat[HDIM + f] = b[f] - mu * A;
}

__global__ void bnapply_kernel(const float* __restrict__ h, __half* __restrict__ h16,
                               const float* __restrict__ stat) {
    const int cq = threadIdx.x & 63;
    const int ro = threadIdx.x >> 6;
    const float4 Av = *(const float4*)(stat + 4 * cq);
    const float4 Cv = *(const float4*)(stat + HDIM + 4 * cq);
    const float4* h4 = (const float4*)h;
    __half2* o2 = (__half2*)h16;
    const int row0 = blockIdx.x * 32 + ro * 8;
    #pragma unroll
    for (int i = 0; i < 8; i++) {
        size_t idx = (size_t)(row0 + i) * 64 + cq;
        float4 v = h4[idx];
        o2[2 * idx]     = __floats2half2_rn(v.x * Av.x + Cv.x, v.y * Av.y + Cv.y);
        o2[2 * idx + 1] = __floats2half2_rn(v.z * Av.z + Cv.z, v.w * Av.w + Cv.w);
    }
}

// ---------------- fp16 flash attention (3-buffer KV ring) -------------------
#define ATTN_SMEM ((3 * 64 * 56 + 3 * 64 * 56 + 128 * 72) * 2)

__global__ __launch_bounds__(256)
void attn_h_kernel(const __half* __restrict__ qkv, __half* __restrict__ out) {
    extern __shared__ __half hsm[];
    __half (*Kh)[64][56] = (__half(*)[64][56])hsm;
    __half (*Vh)[64][56] = (__half(*)[64][56])(hsm + 3 * 64 * 56);
    __half (*Sh)[72]     = (__half(*)[72])(hsm + 6 * 64 * 56);
    __half* Qs = (__half*)Sh;

    const int qt = blockIdx.x, nh = blockIdx.y, b = blockIdx.z;
    const int tid  = threadIdx.x;
    const int lane = tid & 31;
    const int w    = tid >> 5;
    const int g    = lane >> 2;
    const int tig  = lane & 3;
    const float scale = 0.17677669529663687f;
    const float L2E = 1.4426950408889634f;

    const size_t rowb = (size_t)(b * 1024) * 768 + nh * 32;

    {
        size_t qoff = rowb + (size_t)(qt * 128) * 768;
        #pragma unroll
        for (int i = 0; i < 2; i++) {
            int idx = tid + i * 256;
            int r = idx >> 2, qd = idx & 3;
            cp_async16(Qs + r * 56 + qd * 8, qkv + qoff + (size_t)r * 768 + qd * 8);
        }
        CP_COMMIT();
    }
    {
        int r = tid >> 2, qd = tid & 3;
        cp_async16(&Kh[0][r][qd * 8], qkv + rowb + (size_t)r * 768 + 256 + qd * 8);
        cp_async16(&Vh[0][r][qd * 8], qkv + rowb + (size_t)r * 768 + 512 + qd * 8);
        CP_COMMIT();
    }
    CP_WAIT1();
    __syncthreads();

    unsigned q[2][4];
    {
        unsigned qA = (unsigned)__cvta_generic_to_shared(Qs)
                    + (unsigned)(w * 16 + (lane & 15)) * 112 + ((lane >> 4) << 4);
        LDSM4(q[0][0], q[0][1], q[0][2], q[0][3], qA);
        LDSM4(q[1][0], q[1][1], q[1][2], q[1][3], qA + 32);
    }
    __syncthreads();

    const unsigned kLane = (unsigned)(((lane >> 4) << 3) + (lane & 7)) * 112
                         + (((lane >> 3) & 1) << 4);
    const unsigned pLane = (unsigned)(w * 16 + (lane & 15)) * 144 + ((lane >> 4) << 4);
    const unsigned vLane = (unsigned)((((lane >> 3) & 1) << 3) + (lane & 7)) * 112
                         + ((lane >> 4) << 4);
    const unsigned pBase = (unsigned)__cvta_generic_to_shared(&Sh[0][0]) + pLane;
    const int r0 = w * 16 + g;

    float m0 = -1e30f, m1 = -1e30f, l0 = 0.f, l1 = 0.f;
    float o[4][4] = {};

    for (int kt = 0; kt < 16; kt++) {
        if (kt + 1 < 16) {
            size_t koff = rowb + (size_t)((kt + 1) * 64) * 768;
            int st = (kt + 1) % 3;
            int r = tid >> 2, qd = tid & 3;
            cp_async16(&Kh[st][r][qd * 8], qkv + koff + (size_t)r * 768 + 256 + qd * 8);
            cp_async16(&Vh[st][r][qd * 8], qkv + koff + (size_t)r * 768 + 512 + qd * 8);
            CP_COMMIT();
            CP_WAIT1();
        } else {
            CP_WAIT0();
        }
        __syncthreads();

        const int cb = kt % 3;
        const unsigned kBase = (unsigned)__cvta_generic_to_shared(&Kh[cb][0][0]) + kLane;
        const unsigned vBase = (unsigned)__cvta_generic_to_shared(&Vh[cb][0][0]) + vLane;

        float s[8][4] = {};
        #pragma unroll
        for (int ks = 0; ks < 2; ks++) {
            #pragma unroll
            for (int grp = 0; grp < 4; grp++) {
                unsigned b0, b1, b2, b3;
                LDSM4(b0, b1, b2, b3, kBase + grp * (16 * 112) + ks * 32);
                MMA_F16(s[grp*2  ][0], s[grp*2  ][1], s[grp*2  ][2], s[grp*2  ][3],
                        q[ks][0], q[ks][1], q[ks][2], q[ks][3], b0, b1);
                MMA_F16(s[grp*2+1][0], s[grp*2+1][1], s[grp*2+1][2], s[grp*2+1][3],
                        q[ks][0], q[ks][1], q[ks][2], q[ks][3], b2, b3);
            }
        }

        float rmax0 = -1e30f, rmax1 = -1e30f;
        #pragma unroll
        for (int nt = 0; nt < 8; nt++) {
            s[nt][0] *= scale; s[nt][1] *= scale;
            s[nt][2] *= scale; s[nt][3] *= scale;
            rmax0 = fmaxf(rmax0, fmaxf(s[nt][0], s[nt][1]));
            rmax1 = fmaxf(rmax1, fmaxf(s[nt][2], s[nt][3]));
        }
        rmax0 = fmaxf(rmax0, __shfl_xor_sync(0xffffffffu, rmax0, 1));
        rmax0 = fmaxf(rmax0, __shfl_xor_sync(0xffffffffu, rmax0, 2));
        rmax1 = fmaxf(rmax1, __shfl_xor_sync(0xffffffffu, rmax1, 1));
        rmax1 = fmaxf(rmax1, __shfl_xor_sync(0xffffffffu, rmax1, 2));

        float mn0 = fmaxf(m0, rmax0), mn1 = fmaxf(m1, rmax1);
        float cor0 = __expf(m0 - mn0), cor1 = __expf(m1 - mn1);
        m0 = mn0; m1 = mn1;
        const float mL0 = mn0 * L2E, mL1 = mn1 * L2E;

        float ps0 = 0.f, ps1 = 0.f;
        #pragma unroll
        for (int nt = 0; nt < 8; nt++) {
            __half2 hp0 = h2exp2(__floats2half2_rn(fmaf(s[nt][0], L2E, -mL0),
                                                   fmaf(s[nt][1], L2E, -mL0)));
            __half2 hp1 = h2exp2(__floats2half2_rn(fmaf(s[nt][2], L2E, -mL1),
                                                   fmaf(s[nt][3], L2E, -mL1)));
            int c = nt * 8 + 2 * tig;
            *(__half2*)&Sh[r0    ][c] = hp0;
            *(__half2*)&Sh[r0 + 8][c] = hp1;
            float2 p0 = __half22float2(hp0);
            float2 p1 = __half22float2(hp1);
            ps0 += p0.x + p0.y;
            ps1 += p1.x + p1.y;
        }
        ps0 += __shfl_xor_sync(0xffffffffu, ps0, 1);
        ps0 += __shfl_xor_sync(0xffffffffu, ps0, 2);
        ps1 += __shfl_xor_sync(0xffffffffu, ps1, 1);
        ps1 += __shfl_xor_sync(0xffffffffu, ps1, 2);
        l0 = l0 * cor0 + ps0;
        l1 = l1 * cor1 + ps1;
        #pragma unroll
        for (int nt = 0; nt < 4; nt++) {
            o[nt][0] *= cor0; o[nt][1] *= cor0;
            o[nt][2] *= cor1; o[nt][3] *= cor1;
        }
        __syncwarp();

        #pragma unroll
        for (int ks = 0; ks < 4; ks++) {
            unsigned a0, a1, a2, a3;
            LDSM4(a0, a1, a2, a3, pBase + ks * 32);
            #pragma unroll
            for (int dg = 0; dg < 2; dg++) {
                unsigned v0, v1, v2, v3;
                LDSM4T(v0, v1, v2, v3, vBase + ks * (16 * 112) + dg * 32);
                MMA_F16(o[dg*2  ][0], o[dg*2  ][1], o[dg*2  ][2], o[dg*2  ][3],
                        a0, a1, a2, a3, v0, v1);
                MMA_F16(o[dg*2+1][0], o[dg*2+1][1], o[dg*2+1][2], o[dg*2+1][3],
                        a0, a1, a2, a3, v2, v3);
            }
        }
    }

    const float inv0 = 1.0f / l0, inv1 = 1.0f / l1;
    const int row0 = b * 1024 + qt * 128 + w * 16 + g;
    #pragma unroll
    for (int nt = 0; nt < 4; nt++) {
        const int col = nh * 32 + nt * 8 + 2 * tig;
        size_t i0 = (size_t)row0 * HDIM + col;
        size_t i1 = (size_t)(row0 + 8) * HDIM + col;
        *(__half2*)(out + i0) = __floats2half2_rn(o[nt][0] * inv0, o[nt][1] * inv0);
        *(__half2*)(out + i1) = __floats2half2_rn(o[nt][2] * inv1, o[nt][3] * inv1);
    }
}

// ---------------- head final ------------------------------------------------
__global__ void head_final_kernel(const float* __restrict__ t, const float* __restrict__ w,
                                  const float* __restrict__ b, float* __restrict__ out) {
    int row = blockIdx.x * 8 + (threadIdx.x >> 5);
    int lane = threadIdx.x & 31;
    float acc = 0.f;
    #pragma unroll
    for (int i = lane; i < 128; i += 32)
        acc += t[(size_t)row * 128 + i] * w[i];
    #pragma unroll
    for (int ofs = 16; ofs; ofs >>= 1)
        acc += __shfl_xor_sync(0xffffffffu, acc, ofs);
    if (lane == 0)
        out[row] = 1.0f / (1.0f + expf(-(acc + b[0])));
}

// ---------------- host orchestration ----------------------------------------
extern "C" void kernel_launch(void* const* d_in, const int* in_sizes, int n_in,
                              void* d_out, int out_size) {
    const float* x        = (const float*)d_in[0];
    const int*   erow     = (const int*)  d_in[1];
    const int*   ecol     = (const int*)  d_in[2];
    const float* eval     = (const float*)d_in[3];
    const float* pe       = (const float*)d_in[4];
    const float* W_in     = (const float*)d_in[5];
    const float* b_in     = (const float*)d_in[6];
    const float* W_pe     = (const float*)d_in[7];
    const float* b_pe     = (const float*)d_in[8];
    const float* gcn_W    = (const float*)d_in[9];
    const float* ain_W    = (const float*)d_in[10];
    const float* ain_b    = (const float*)d_in[11];
    const float* aout_W   = (const float*)d_in[12];
    const float* aout_b   = (const float*)d_in[13];
    const float* bn_g     = (const float*)d_in[14];
    const float* bn_b     = (const float*)d_in[15];
    const float* ffn_W1   = (const float*)d_in[16];
    const float* ffn_b1   = (const float*)d_in[17];
    const float* ffn_W2   = (const float*)d_in[18];
    const float* ffn_b2   = (const float*)d_in[19];
    const float* head_W1  = (const float*)d_in[20];
    const float* head_b1  = (const float*)d_in[21];
    const float* head_W2  = (const float*)d_in[22];
    const float* head_b2  = (const float*)d_in[23];

    float *h, *t1, *psum, *psq, *stat;
    __half *w16, *x16, *pe16, *h16, *t1h, *t2h;
    int *cnt, *slot;
    cudaGetSymbolAddress((void**)&h,      g_h);
    cudaGetSymbolAddress((void**)&t1,     g_t1);
    cudaGetSymbolAddress((void**)&psum,   g_psum);
    cudaGetSymbolAddress((void**)&psq,    g_psq);
    cudaGetSymbolAddress((void**)&stat,   g_stat);
    cudaGetSymbolAddress((void**)&cnt,    g_cnt);
    cudaGetSymbolAddress((void**)&slot,   g_slot);
    cudaGetSymbolAddress((void**)&w16,    g_w16);
    cudaGetSymbolAddress((void**)&x16,    g_x16);
    cudaGetSymbolAddress((void**)&pe16,   g_pe16);
    cudaGetSymbolAddress((void**)&h16,    g_h16);
    cudaGetSymbolAddress((void**)&t1h,    g_t1h);
    cudaGetSymbolAddress((void**)&t2h,    g_t2h);

    cudaFuncSetAttribute(attn_h_kernel,
                         cudaFuncAttributeMaxDynamicSharedMemorySize, ATTN_SMEM);
    cudaFuncSetAttribute(gemm_h_kernel<64, 0, 0, false, 1, true>,
                         cudaFuncAttributeMaxDynamicSharedMemorySize, GEMM_SMEM_64);
    cudaFuncSetAttribute(gemm_h_kernel<64, 0, 0, false, 2, false>,
                         cudaFuncAttributeMaxDynamicSharedMemorySize, GEMM_SMEM_64);
    cudaFuncSetAttribute(gemm_h_kernel<64, 0, 2, true, 0, false>,
                         cudaFuncAttributeMaxDynamicSharedMemorySize, GEMM_SMEM_64);
    cudaFuncSetAttribute(gemm_h_kernel<64, 1, 0, false, 0, false>,
                         cudaFuncAttributeMaxDynamicSharedMemorySize, GEMM_SMEM_64);
    cudaFuncSetAttribute(gemm_h_kernel<128, 0, 0, false, 2, false>,
                         cudaFuncAttributeMaxDynamicSharedMemorySize, GEMM_SMEM_128);
    cudaFuncSetAttribute(gemm_h_kernel<128, 1, 0, false, 2, false>,
                         cudaFuncAttributeMaxDynamicSharedMemorySize, GEMM_SMEM_128);

    // batched fp16 conversion (inputs + all weights, single launch)
    {
        ConvSegs segs;
        const float* srcs[NSEG] = {x, pe, W_in, W_pe, gcn_W, ain_W, aout_W,
                                   ffn_W1, ffn_W2, head_W1};
        __half* dsts[NSEG] = {x16, pe16, w16 + OFF_WIN, w16 + OFF_WPE,
                              w16 + OFF_GCN, w16 + OFF_AIN, w16 + OFF_AOUT,
                              w16 + OFF_FFN1, w16 + OFF_FFN2, w16 + OFF_HW1};
        int cnts[NSEG] = {BNODES * 128, BNODES * 8, HDIM * 128, HDIM * 8,
                          NLAYER * HDIM * HDIM, NLAYER * 768 * HDIM,
                          NLAYER * HDIM * HDIM, NLAYER * 1024 * HDIM,
                          NLAYER * HDIM * 1024, 128 * HDIM};
        int cum = 0;
        for (int i = 0; i < NSEG; i++) {
            segs.src[i] = srcs[i];
            segs.dst[i] = dsts[i];
            segs.cum4[i] = cum;
            cum += cnts[i] / 4;
        }
        segs.cum4[NSEG] = cum;
        f2h_multi_kernel<<<(cum + 255) / 256, 256>>>(segs, cum);
    }

    // CSR build: single fused count+fill
    cudaMemsetAsync(cnt, 0, BNODES * sizeof(int));
    count_fill_kernel<<<NEDGE / 256, 256>>>(erow, cnt, slot);

    const dim3 g256 (2, BNODES / 64);
    const dim3 g768 (6, BNODES / 128);
    const dim3 g1024(8, BNODES / 128);
    const dim3 g128 (1, BNODES / 64);

    // input projection: single GEMM with fused rank-8 pe update
    gemm_h_kernel<64, 0, 0, false, 1, true><<<g256, 256, GEMM_SMEM_64>>>(
        x16, w16 + OFF_WIN, b_in, h, h16, nullptr,
        pe16, w16 + OFF_WPE, b_pe, 128, HDIM);

    for (int l = 0; l < NLAYER; l++) {
        // ---- local GCN ----
        gemm_h_kernel<64, 0, 0, false, 2, false><<<g256, 256, GEMM_SMEM_64>>>(
            h16, w16 + OFF_GCN + (size_t)l * HDIM * HDIM, nullptr,
            nullptr, t1h, nullptr, nullptr, nullptr, nullptr, HDIM, HDIM);
        gcn_gather_kernel<<<BNODES, 128>>>(t1h, cnt, slot, ecol, eval, t2h);
        if (l == 0) bnpre_kernel<true ><<<256, 256>>>(h, t2h, psum, psq, stat);
        else        bnpre_kernel<false><<<256, 256>>>(h, t2h, psum, psq, stat);
        bnstat_kernel<<<2, 128>>>(psum, psq, bn_g + l * 3 * HDIM,
                                  bn_b + l * 3 * HDIM, stat, 256);
        bnapply_kernel<<<256, 256>>>(h, h16, stat);
        // ---- global attention ----
        gemm_h_kernel<128, 0, 0, false, 2, false><<<g768, 256, GEMM_SMEM_128>>>(
            h16, w16 + OFF_AIN + (size_t)l * 768 * HDIM, ain_b + l * 768,
            nullptr, t1h, nullptr, nullptr, nullptr, nullptr, HDIM, 768);
        attn_h_kernel<<<dim3(8, 8, 8), 256, ATTN_SMEM>>>(t1h, t2h);
        gemm_h_kernel<64, 0, 2, true, 0, false><<<g256, 256, GEMM_SMEM_64>>>(
            t2h, w16 + OFF_AOUT + (size_t)l * HDIM * HDIM, aout_b + l * HDIM,
            h, nullptr, stat, nullptr, nullptr, nullptr, HDIM, HDIM);
        bnstat_kernel<<<2, 128>>>(psum, psq, bn_g + l * 3 * HDIM + HDIM,
                                  bn_b + l * 3 * HDIM + HDIM, stat, 128);
        bnapply_kernel<<<256, 256>>>(h, h16, stat);
        // ---- FFN ----
        gemm_h_kernel<128, 1, 0, false, 2, false><<<g1024, 256, GEMM_SMEM_128>>>(
            h16, w16 + OFF_FFN1 + (size_t)l * 1024 * HDIM, ffn_b1 + l * 1024,
            nullptr, t1h, nullptr, nullptr, nullptr, nullptr, HDIM, 1024);
        gemm_h_kernel<64, 0, 2, true, 0, false><<<g256, 256, GEMM_SMEM_64>>>(
            t1h, w16 + OFF_FFN2 + (size_t)l * HDIM * 1024, ffn_b2 + l * HDIM,
            h, nullptr, stat, nullptr, nullptr, nullptr, 1024, HDIM);
        bnstat_kernel<<<2, 128>>>(psum, psq, bn_g + l * 3 * HDIM + 2 * HDIM,
                                  bn_b + l * 3 * HDIM + 2 * HDIM, stat, 128);
        bnapply_kernel<<<256, 256>>>(h, h16, stat);
    }

    // ---- head ----
    gemm_h_kernel<64, 1, 0, false, 0, false><<<g128, 256, GEMM_SMEM_64>>>(
        h16, w16 + OFF_HW1, head_b1, t1, nullptr, nullptr,
        nullptr, nullptr, nullptr, HDIM, 128);
    head_final_kernel<<<BNODES / 8, 256>>>(t1, head_W2, head_b2, (float*)d_out);
}